// round 7
// baseline (speedup 1.0000x reference)
#include <cuda_runtime.h>
#include <math.h>
#include <stdint.h>

// Shapes (fixed)
#define D_HID 1024
#define SEQ   2048
#define BATCH 2
#define HEADS 16
#define HD    64
#define MROWS (BATCH*SEQ)                 // 4096
#define OUT_MAIN (MROWS*D_HID)            // 4194304
#define ATTN_ELEMS (MROWS*HEADS*HEADS)    // 1048576

// fp32 scratch
__device__ float g_q [MROWS*D_HID];
__device__ float g_k [MROWS*D_HID];
__device__ float g_v [MROWS*D_HID];
__device__ float g_xs[MROWS*D_HID];
__device__ float g_cos[SEQ*(D_HID/2)];
__device__ float g_sin[SEQ*(D_HID/2)];

// int8 digit planes + scales
__device__ int8_t g_in0[MROWS*D_HID];
__device__ int8_t g_in1[MROWS*D_HID];
__device__ int8_t g_cx0[MROWS*D_HID];
__device__ int8_t g_cx1[MROWS*D_HID];
__device__ int8_t g_xs0[MROWS*D_HID];
__device__ int8_t g_xs1[MROWS*D_HID];
__device__ int8_t g_w0[4*D_HID*D_HID];    // W^T digit0, 4 weights
__device__ int8_t g_w1[4*D_HID*D_HID];    // W^T digit1
__device__ float g_sc_in[MROWS];
__device__ float g_sc_cx[MROWS];
__device__ float g_sc_xs[MROWS];
__device__ float g_sc_w[4*D_HID];

__device__ __forceinline__ uint32_t smem_u32(const void* p) {
    uint32_t a;
    asm("{ .reg .u64 t; cvta.to.shared.u64 t, %1; cvt.u32.u64 %0, t; }"
        : "=r"(a) : "l"(p));
    return a;
}

// ---------------------------------------------------------------------------
// RoPE tables
// ---------------------------------------------------------------------------
__global__ void rope_tables_kernel() {
    int idx = blockIdx.x * blockDim.x + threadIdx.x;   // SEQ*512
    int s = idx >> 9;
    int j = idx & 511;
    float inv = expf(-(float)j * (9.210340371976184f / 512.0f));
    float arg = (float)s * inv;
    float sv, cv;
    sincosf(arg, &sv, &cv);
    g_cos[idx] = cv;
    g_sin[idx] = sv;
}

// ---------------------------------------------------------------------------
// Per-row fp32 -> 2x int8 digit quantization: x = sc*(d0 + d1/128) + eps
// One block (256 thr) per row of 1024.
// ---------------------------------------------------------------------------
__global__ __launch_bounds__(256) void quant_act(const float* __restrict__ src,
                                                 int8_t* __restrict__ d0,
                                                 int8_t* __restrict__ d1,
                                                 float* __restrict__ sc)
{
    __shared__ float red[8];
    int row = blockIdx.x;
    int tid = threadIdx.x;
    const float4* s4 = (const float4*)(src + (size_t)row * D_HID);
    float4 v = s4[tid];
    float m = fmaxf(fmaxf(fabsf(v.x), fabsf(v.y)), fmaxf(fabsf(v.z), fabsf(v.w)));
    #pragma unroll
    for (int o = 16; o; o >>= 1) m = fmaxf(m, __shfl_xor_sync(0xffffffffu, m, o));
    if ((tid & 31) == 0) red[tid >> 5] = m;
    __syncthreads();
    if (tid == 0) {
        float t = red[0];
        #pragma unroll
        for (int i = 1; i < 8; i++) t = fmaxf(t, red[i]);
        red[0] = fmaxf(t, 1e-30f);
    }
    __syncthreads();
    float bmax = red[0];
    float inv = 127.0f / bmax;

    float q, i0, i1;
    char4 c0, c1;
    q = v.x * inv; i0 = rintf(q); i1 = rintf((q - i0) * 128.0f);
    c0.x = (signed char)(int)i0; c1.x = (signed char)(int)i1;
    q = v.y * inv; i0 = rintf(q); i1 = rintf((q - i0) * 128.0f);
    c0.y = (signed char)(int)i0; c1.y = (signed char)(int)i1;
    q = v.z * inv; i0 = rintf(q); i1 = rintf((q - i0) * 128.0f);
    c0.z = (signed char)(int)i0; c1.z = (signed char)(int)i1;
    q = v.w * inv; i0 = rintf(q); i1 = rintf((q - i0) * 128.0f);
    c0.w = (signed char)(int)i0; c1.w = (signed char)(int)i1;

    ((char4*)(d0 + (size_t)row * D_HID))[tid] = c0;
    ((char4*)(d1 + (size_t)row * D_HID))[tid] = c1;
    if (tid == 0) sc[row] = bmax * (1.0f / 127.0f);
}

// ---------------------------------------------------------------------------
// Column-max of each weight (rows of W^T): scale per output feature
// grid (32 colgroups, 4 weights), block (32, 8)
// ---------------------------------------------------------------------------
__global__ __launch_bounds__(256) void colmax_w(const float* __restrict__ W0,
                                                const float* __restrict__ W1,
                                                const float* __restrict__ W2,
                                                const float* __restrict__ W3)
{
    __shared__ float t[8][32];
    int z = blockIdx.y;
    const float* W = (z == 0) ? W0 : (z == 1) ? W1 : (z == 2) ? W2 : W3;
    int tx = threadIdx.x, ty = threadIdx.y;
    int col = blockIdx.x * 32 + tx;
    float m = 0.0f;
    for (int k = ty; k < D_HID; k += 8)
        m = fmaxf(m, fabsf(W[(size_t)k * D_HID + col]));
    t[ty][tx] = m;
    __syncthreads();
    if (ty == 0) {
        #pragma unroll
        for (int i = 1; i < 8; i++) m = fmaxf(m, t[i][tx]);
        g_sc_w[z * D_HID + col] = fmaxf(m, 1e-30f) * (1.0f / 127.0f);
    }
}

// ---------------------------------------------------------------------------
// Weight transpose + 2-digit int8 quantization (uses g_sc_w)
// ---------------------------------------------------------------------------
__global__ __launch_bounds__(256) void quant_wt4(const float* __restrict__ W0,
                                                 const float* __restrict__ W1,
                                                 const float* __restrict__ W2,
                                                 const float* __restrict__ W3)
{
    __shared__ float t[32][33];
    int z = blockIdx.z;
    const float* W = (z == 0) ? W0 : (z == 1) ? W1 : (z == 2) ? W2 : W3;
    int8_t* w0 = g_w0 + (size_t)z * D_HID * D_HID;
    int8_t* w1 = g_w1 + (size_t)z * D_HID * D_HID;
    int x0 = blockIdx.x * 32;
    int y0 = blockIdx.y * 32;
    int tx = threadIdx.x, ty = threadIdx.y;   // (32,8)
    #pragma unroll
    for (int j = 0; j < 4; j++)
        t[ty + 8 * j][tx] = W[(size_t)(y0 + ty + 8 * j) * D_HID + x0 + tx];
    __syncthreads();
    #pragma unroll
    for (int j = 0; j < 4; j++) {
        int r = ty + 8 * j;
        int n = x0 + r;
        float v = t[tx][r];
        float inv = 1.0f / g_sc_w[z * D_HID + n];
        float q = v * inv;
        float i0 = rintf(q);
        float i1 = rintf((q - i0) * 128.0f);
        size_t o = (size_t)n * D_HID + y0 + tx;
        w0[o] = (signed char)(int)i0;
        w1[o] = (signed char)(int)i1;
    }
}

// ---------------------------------------------------------------------------
// int8 2-digit GEMM: C = sa_m * sb_n * (sum d0*w0 + sum(d0*w1 + d1*w0)/128) + bias
//   CTA 128x128, 8 warps of 32x64, chunk = 64 int8 (2 x k32), 3-stage cp.async.
//   mma.sync.m16n8k32.s8 -> s32 (exact). 3 IMMA per k32 slab.
// ---------------------------------------------------------------------------
#define KC8 64
#define NSTAGE 3
#define PLANE 8192                       // 128 rows * 64B
#define STAGE_BYTES (4*PLANE)            // A0, A1, B0, B1 = 32768
#define GEMM_SMEM (NSTAGE*STAGE_BYTES)   // 98304
#define NCHUNK (D_HID/KC8)               // 16

#define LDSM4(r0,r1,r2,r3,addr) \
    asm volatile("ldmatrix.sync.aligned.m8n8.x4.shared.b16 {%0,%1,%2,%3}, [%4];" \
        : "=r"(r0), "=r"(r1), "=r"(r2), "=r"(r3) : "r"(addr))

#define MMA_S8(d, a, b0v, b1v) \
    asm volatile("mma.sync.aligned.m16n8k32.row.col.s32.s8.s8.s32 " \
        "{%0,%1,%2,%3}, {%4,%5,%6,%7}, {%8,%9}, {%0,%1,%2,%3};" \
        : "+r"((d)[0]), "+r"((d)[1]), "+r"((d)[2]), "+r"((d)[3]) \
        : "r"((a)[0]), "r"((a)[1]), "r"((a)[2]), "r"((a)[3]), "r"(b0v), "r"(b1v))

__global__ __launch_bounds__(256, 1)
void gemm_i8(const int8_t* __restrict__ A0, const int8_t* __restrict__ A1,
             const int8_t* __restrict__ B0, const int8_t* __restrict__ B1,
             const float* __restrict__ sa, const float* __restrict__ sb,
             const float* __restrict__ bias, float* __restrict__ C)
{
    extern __shared__ char smem[];
    uint32_t sbase = smem_u32(smem);
    int tid = threadIdx.x, lane = tid & 31, wid = tid >> 5;
    int wm = (wid & 3) * 32;        // 4 M-warps over 128
    int wn = (wid >> 2) * 64;       // 2 N-warps over 128

    int mbaseA = blockIdx.y * 128;
    int nbaseB = blockIdx.x * 128;

    // loader mapping: 256 threads, 2 x 16B per plane per chunk
    int lrow = tid >> 1;            // 0..127
    int lb0  = (tid & 1) * 2;       // 16B block pair
    int lsw  = (lrow >> 1) & 3;

    // ldmatrix lane addressing (identical byte-geometry to validated bf16 path)
    uint32_t aOff[2]; int aSw[2];
    #pragma unroll
    for (int mt = 0; mt < 2; mt++) {
        int r = wm + mt * 16 + (lane & 7) + ((lane >> 3) & 1) * 8;
        aOff[mt] = r * 64;
        aSw[mt] = (r >> 1) & 3;
    }
    int g = lane >> 3;
    uint32_t bOff[4]; int bSw[4];
    #pragma unroll
    for (int pk = 0; pk < 4; pk++) {
        int r = wn + pk * 16 + ((g >> 1) << 3) + (lane & 7);
        bOff[pk] = r * 64;
        bSw[pk] = (r >> 1) & 3;
    }
    int aKb = lane >> 4;
    int bKb = g & 1;

    int acc00[2][8][4];
    int accX [2][8][4];
    #pragma unroll
    for (int i = 0; i < 2; i++)
        #pragma unroll
        for (int j = 0; j < 8; j++)
            #pragma unroll
            for (int c = 0; c < 4; c++) { acc00[i][j][c] = 0; accX[i][j][c] = 0; }

    #define LOAD_CHUNK(chunk) do {                                               \
        uint32_t st0 = sbase + ((chunk) % NSTAGE) * STAGE_BYTES;                 \
        int kk = (chunk) * KC8;                                                  \
        const int8_t* sa0 = A0 + (size_t)(mbaseA + lrow) * D_HID + kk;           \
        const int8_t* sa1 = A1 + (size_t)(mbaseA + lrow) * D_HID + kk;           \
        const int8_t* sb0 = B0 + (size_t)(nbaseB + lrow) * D_HID + kk;           \
        const int8_t* sb1 = B1 + (size_t)(nbaseB + lrow) * D_HID + kk;           \
        _Pragma("unroll")                                                        \
        for (int j = 0; j < 2; j++) {                                            \
            int blk = lb0 + j;                                                   \
            uint32_t d = st0 + lrow * 64 + ((blk ^ lsw) << 4);                   \
            asm volatile("cp.async.cg.shared.global [%0], [%1], 16;"             \
                         :: "r"(d), "l"(sa0 + blk * 16));                        \
            asm volatile("cp.async.cg.shared.global [%0], [%1], 16;"             \
                         :: "r"(d + PLANE), "l"(sa1 + blk * 16));                \
            asm volatile("cp.async.cg.shared.global [%0], [%1], 16;"             \
                         :: "r"(d + 2 * PLANE), "l"(sb0 + blk * 16));            \
            asm volatile("cp.async.cg.shared.global [%0], [%1], 16;"             \
                         :: "r"(d + 3 * PLANE), "l"(sb1 + blk * 16));            \
        }                                                                        \
    } while (0)

    #pragma unroll
    for (int s = 0; s < NSTAGE - 1; s++) {
        LOAD_CHUNK(s);
        asm volatile("cp.async.commit_group;");
    }

    for (int i = 0; i < NCHUNK; i++) {
        asm volatile("cp.async.wait_group %0;" :: "n"(NSTAGE - 2));
        __syncthreads();

        if (i + NSTAGE - 1 < NCHUNK)
            LOAD_CHUNK(i + NSTAGE - 1);
        asm volatile("cp.async.commit_group;");

        uint32_t st = sbase + (i % NSTAGE) * STAGE_BYTES;
        #pragma unroll
        for (int s = 0; s < 2; s++) {   // two k32 slabs per 64B chunk
            uint32_t a0f[2][4], a1f[2][4];
            #pragma unroll
            for (int mt = 0; mt < 2; mt++) {
                uint32_t ad = st + aOff[mt] + (((2 * s + aKb) ^ aSw[mt]) << 4);
                LDSM4(a0f[mt][0], a0f[mt][1], a0f[mt][2], a0f[mt][3], ad);
                LDSM4(a1f[mt][0], a1f[mt][1], a1f[mt][2], a1f[mt][3], ad + PLANE);
            }
            uint32_t b0f[16], b1f[16];
            #pragma unroll
            for (int pk = 0; pk < 4; pk++) {
                uint32_t ad = st + 2 * PLANE + bOff[pk]
                            + (((2 * s + bKb) ^ bSw[pk]) << 4);
                LDSM4(b0f[pk*4+0], b0f[pk*4+1], b0f[pk*4+2], b0f[pk*4+3], ad);
                LDSM4(b1f[pk*4+0], b1f[pk*4+1], b1f[pk*4+2], b1f[pk*4+3], ad + PLANE);
            }
            #pragma unroll
            for (int mt = 0; mt < 2; mt++)
                #pragma unroll
                for (int nt = 0; nt < 8; nt++)
                    MMA_S8(acc00[mt][nt], a0f[mt], b0f[nt*2], b0f[nt*2+1]);
            #pragma unroll
            for (int mt = 0; mt < 2; mt++)
                #pragma unroll
                for (int nt = 0; nt < 8; nt++)
                    MMA_S8(accX[mt][nt], a0f[mt], b1f[nt*2], b1f[nt*2+1]);
            #pragma unroll
            for (int mt = 0; mt < 2; mt++)
                #pragma unroll
                for (int nt = 0; nt < 8; nt++)
                    MMA_S8(accX[mt][nt], a1f[mt], b0f[nt*2], b0f[nt*2+1]);
        }
    }

    // epilogue: combine digits with row/col scales
    #pragma unroll
    for (int mt = 0; mt < 2; mt++) {
        int row0 = blockIdx.y * 128 + wm + mt * 16 + (lane >> 2);
        float sa0 = sa[row0], sa1 = sa[row0 + 8];
        #pragma unroll
        for (int nt = 0; nt < 8; nt++) {
            int col = blockIdx.x * 128 + wn + nt * 8 + (lane & 3) * 2;
            float sb0 = sb[col], sb1 = sb[col + 1];
            float b0 = bias[col], b1 = bias[col + 1];
            float2 v0, v1;
            v0.x = sa0 * sb0 * ((float)acc00[mt][nt][0] + (float)accX[mt][nt][0] * (1.0f/128.0f)) + b0;
            v0.y = sa0 * sb1 * ((float)acc00[mt][nt][1] + (float)accX[mt][nt][1] * (1.0f/128.0f)) + b1;
            v1.x = sa1 * sb0 * ((float)acc00[mt][nt][2] + (float)accX[mt][nt][2] * (1.0f/128.0f)) + b0;
            v1.y = sa1 * sb1 * ((float)acc00[mt][nt][3] + (float)accX[mt][nt][3] * (1.0f/128.0f)) + b1;
            *(float2*)(C + (size_t)row0 * D_HID + col) = v0;
            *(float2*)(C + (size_t)(row0 + 8) * D_HID + col) = v1;
        }
    }
}

// ---------------------------------------------------------------------------
// Fused: RoPE(q,k) + per-token head attention (16x16) + attn output +
// scrambled fp32 ctx:  xs[b, h*128 + s/16, (s%16)*64 + d] = ctx[b, s, h, d]
// ---------------------------------------------------------------------------
__global__ __launch_bounds__(256) void attn_fused_kernel(float* __restrict__ attn_out,
                                                         int write_attn)
{
    __shared__ float sq[16][65];
    __shared__ float sk[16][65];
    __shared__ float sv[16][65];
    __shared__ float sc[16][17];

    int token = blockIdx.x;
    int tid   = threadIdx.x;
    int s     = token & (SEQ - 1);
    int b     = token >> 11;

    const float* qrow = g_q + (size_t)token * D_HID;
    const float* krow = g_k + (size_t)token * D_HID;
    const float* vrow = g_v + (size_t)token * D_HID;

    for (int i = tid; i < D_HID; i += 256) {
        int j  = i & 511;
        float c  = g_cos[(s << 9) | j];
        float sn = g_sin[(s << 9) | j];
        float qa = qrow[i], qb = qrow[i ^ 512];
        float ka = krow[i], kb = krow[i ^ 512];
        float rq, rk;
        if (i < 512) { rq = qa * c - qb * sn; rk = ka * c - kb * sn; }
        else         { rq = qa * c + qb * sn; rk = ka * c + kb * sn; }
        sq[i >> 6][i & 63] = rq;
        sk[i >> 6][i & 63] = rk;
        sv[i >> 6][i & 63] = vrow[i];
    }
    __syncthreads();

    {
        int h = tid >> 4, t = tid & 15;
        float acc = 0.0f;
        #pragma unroll
        for (int d = 0; d < HD; d++)
            acc = fmaf(sq[h][d], sk[t][d], acc);
        sc[h][t] = acc * 0.125f;
    }
    __syncthreads();

    if (tid < 16) {
        float m = -1e30f;
        #pragma unroll
        for (int t = 0; t < 16; t++) m = fmaxf(m, sc[tid][t]);
        float sum = 0.0f;
        #pragma unroll
        for (int t = 0; t < 16; t++) {
            float e = expf(sc[tid][t] - m);
            sc[tid][t] = e;
            sum += e;
        }
        float r = 1.0f / sum;
        #pragma unroll
        for (int t = 0; t < 16; t++) sc[tid][t] *= r;
    }
    __syncthreads();

    if (write_attn)
        attn_out[(size_t)token * 256 + tid] = sc[tid >> 4][tid & 15];

    int o0 = tid * 4;
    int h  = o0 >> 6;
    int d0 = o0 & 63;
    float* xrow = g_xs + ((size_t)b * SEQ + (h * 128 + (s >> 4))) * D_HID
                       + ((s & 15) << 6);
    #pragma unroll
    for (int jj = 0; jj < 4; jj++) {
        int d = d0 + jj;
        float acc = 0.0f;
        #pragma unroll
        for (int t = 0; t < 16; t++)
            acc = fmaf(sc[h][t], sv[t][d], acc);
        xrow[d] = acc;
    }
}

// ---------------------------------------------------------------------------
extern "C" void kernel_launch(void* const* d_in, const int* in_sizes, int n_in,
                              void* d_out, int out_size)
{
    const float* inputs  = (const float*)d_in[0];
    const float* context = (const float*)d_in[1];
    const float* Wq = (const float*)d_in[2];
    const float* bq = (const float*)d_in[3];
    const float* Wk = (const float*)d_in[4];
    const float* bk = (const float*)d_in[5];
    const float* Wv = (const float*)d_in[6];
    const float* bv = (const float*)d_in[7];
    const float* Wo = (const float*)d_in[8];
    const float* bo = (const float*)d_in[9];
    float* out = (float*)d_out;

    float *q, *k, *v, *xs, *scin, *sccx, *scxs, *scw;
    int8_t *in0, *in1, *cx0, *cx1, *xs0, *xs1, *w0, *w1;
    cudaGetSymbolAddress((void**)&q,    g_q);
    cudaGetSymbolAddress((void**)&k,    g_k);
    cudaGetSymbolAddress((void**)&v,    g_v);
    cudaGetSymbolAddress((void**)&xs,   g_xs);
    cudaGetSymbolAddress((void**)&in0,  g_in0);
    cudaGetSymbolAddress((void**)&in1,  g_in1);
    cudaGetSymbolAddress((void**)&cx0,  g_cx0);
    cudaGetSymbolAddress((void**)&cx1,  g_cx1);
    cudaGetSymbolAddress((void**)&xs0,  g_xs0);
    cudaGetSymbolAddress((void**)&xs1,  g_xs1);
    cudaGetSymbolAddress((void**)&w0,   g_w0);
    cudaGetSymbolAddress((void**)&w1,   g_w1);
    cudaGetSymbolAddress((void**)&scin, g_sc_in);
    cudaGetSymbolAddress((void**)&sccx, g_sc_cx);
    cudaGetSymbolAddress((void**)&scxs, g_sc_xs);
    cudaGetSymbolAddress((void**)&scw,  g_sc_w);

    cudaFuncSetAttribute(gemm_i8,
                         cudaFuncAttributeMaxDynamicSharedMemorySize, GEMM_SMEM);

    const size_t WSZ = (size_t)D_HID * D_HID;
    dim3 ggrid(D_HID / 128, MROWS / 128);   // (8, 32) = 256 CTAs

    // 1) tables + quantization of activations and weights
    rope_tables_kernel<<<(SEQ * 512) / 256, 256>>>();
    quant_act<<<MROWS, 256>>>(inputs,  in0, in1, scin);
    quant_act<<<MROWS, 256>>>(context, cx0, cx1, sccx);
    {
        dim3 cgrid(32, 4), cblk(32, 8);
        colmax_w<<<cgrid, cblk>>>(Wq, Wk, Wv, Wo);
        dim3 wgrid(32, 32, 4), wblk(32, 8);
        quant_wt4<<<wgrid, wblk>>>(Wq, Wk, Wv, Wo);
    }

    // 2) q, k, v projections (int8 2-digit tensor GEMM)
    gemm_i8<<<ggrid, 256, GEMM_SMEM>>>(in0, in1, w0 + 0*WSZ, w1 + 0*WSZ, scin, scw + 0*D_HID, bq, q);
    gemm_i8<<<ggrid, 256, GEMM_SMEM>>>(cx0, cx1, w0 + 1*WSZ, w1 + 1*WSZ, sccx, scw + 1*D_HID, bk, k);
    gemm_i8<<<ggrid, 256, GEMM_SMEM>>>(cx0, cx1, w0 + 2*WSZ, w1 + 2*WSZ, sccx, scw + 2*D_HID, bv, v);

    // 3) fused RoPE + head-attention + scrambled fp32 ctx
    int write_attn = (out_size >= OUT_MAIN + ATTN_ELEMS) ? 1 : 0;
    attn_fused_kernel<<<MROWS, 256>>>(out + OUT_MAIN, write_attn);

    // 4) quantize ctx + final projection
    quant_act<<<MROWS, 256>>>(xs, xs0, xs1, scxs);
    gemm_i8<<<ggrid, 256, GEMM_SMEM>>>(xs0, xs1, w0 + 3*WSZ, w1 + 3*WSZ, scxs, scw + 3*D_HID, bo, out);
}

// round 8
// speedup vs baseline: 2.4014x; 2.4014x over previous
#include <cuda_runtime.h>
#include <cuda_bf16.h>
#include <math.h>
#include <stdint.h>

// Shapes (fixed)
#define D_HID 1024
#define SEQ   2048
#define BATCH 2
#define HEADS 16
#define HD    64
#define MROWS (BATCH*SEQ)                 // 4096
#define OUT_MAIN (MROWS*D_HID)            // 4194304
#define ATTN_ELEMS (MROWS*HEADS*HEADS)    // 1048576

// fp32 scratch
__device__ float g_q [MROWS*D_HID];
__device__ float g_kv[MROWS*2*D_HID];     // packed rows: k[0..1023] | v[1024..2047]
__device__ float g_bkv[2*D_HID];          // bk || bv
__device__ float g_cos[SEQ*(D_HID/2)];
__device__ float g_sin[SEQ*(D_HID/2)];

// bf16 split planes
__device__ __nv_bfloat16 g_in_h[MROWS*D_HID];
__device__ __nv_bfloat16 g_in_l[MROWS*D_HID];
__device__ __nv_bfloat16 g_cx_h[MROWS*D_HID];
__device__ __nv_bfloat16 g_cx_l[MROWS*D_HID];
__device__ __nv_bfloat16 g_xs_h[MROWS*D_HID];
__device__ __nv_bfloat16 g_xs_l[MROWS*D_HID];
__device__ __nv_bfloat16 g_wt_h[4*D_HID*D_HID];   // W^T hi (Wq,Wk,Wv,Wo)
__device__ __nv_bfloat16 g_wt_l[4*D_HID*D_HID];   // W^T lo

__device__ __forceinline__ uint32_t smem_u32(const void* p) {
    uint32_t a;
    asm("{ .reg .u64 t; cvta.to.shared.u64 t, %1; cvt.u32.u64 %0, t; }"
        : "=r"(a) : "l"(p));
    return a;
}

// ---------------------------------------------------------------------------
// Fused prep kernel: one launch does
//   blocks [0,8192)      : fp32->bf16 hi/lo split of inputs (0-4095) / context
//   blocks [8192,12288)  : W transpose + split for 4 weights
//   blocks [12288,16384) : RoPE tables
//   blocks [16384,16392) : pack bk||bv into g_bkv
// ---------------------------------------------------------------------------
__global__ __launch_bounds__(256)
void prep_kernel(const float* __restrict__ inputs, const float* __restrict__ context,
                 const float* __restrict__ W0, const float* __restrict__ W1,
                 const float* __restrict__ W2, const float* __restrict__ W3,
                 const float* __restrict__ bk, const float* __restrict__ bv)
{
    int blk = blockIdx.x;
    int tid = threadIdx.x;

    if (blk < 8192) {
        // activation split (float4 per thread)
        int which = blk >> 12;                      // 0=inputs, 1=context
        int idx = ((blk & 4095) << 8) | tid;        // over n4 = 1048576
        const float4* src = (const float4*)(which ? context : inputs);
        uint2* h = (uint2*)(which ? g_cx_h : g_in_h);
        uint2* l = (uint2*)(which ? g_cx_l : g_in_l);
        float4 v = src[idx];
        __nv_bfloat16 hx = __float2bfloat16_rn(v.x);
        __nv_bfloat16 hy = __float2bfloat16_rn(v.y);
        __nv_bfloat16 hz = __float2bfloat16_rn(v.z);
        __nv_bfloat16 hw = __float2bfloat16_rn(v.w);
        __nv_bfloat16 lx = __float2bfloat16_rn(v.x - __bfloat162float(hx));
        __nv_bfloat16 ly = __float2bfloat16_rn(v.y - __bfloat162float(hy));
        __nv_bfloat16 lz = __float2bfloat16_rn(v.z - __bfloat162float(hz));
        __nv_bfloat16 lw = __float2bfloat16_rn(v.w - __bfloat162float(hw));
        __nv_bfloat162 h01; h01.x = hx; h01.y = hy;
        __nv_bfloat162 h23; h23.x = hz; h23.y = hw;
        __nv_bfloat162 l01; l01.x = lx; l01.y = ly;
        __nv_bfloat162 l23; l23.x = lz; l23.y = lw;
        uint2 uh, ul;
        uh.x = *(uint32_t*)&h01; uh.y = *(uint32_t*)&h23;
        ul.x = *(uint32_t*)&l01; ul.y = *(uint32_t*)&l23;
        h[idx] = uh;
        l[idx] = ul;
    } else if (blk < 12288) {
        // weight transpose + split: 1024 blocks per weight, 32x32 tiles
        __shared__ float t[32][33];
        int r  = blk - 8192;
        int z  = r >> 10;
        int bi = r & 1023;
        int x0 = (bi & 31) * 32;
        int y0 = (bi >> 5) * 32;
        const float* W = (z == 0) ? W0 : (z == 1) ? W1 : (z == 2) ? W2 : W3;
        __nv_bfloat16* h = g_wt_h + (size_t)z * D_HID * D_HID;
        __nv_bfloat16* l = g_wt_l + (size_t)z * D_HID * D_HID;
        int tx = tid & 31, ty = tid >> 5;           // (32,8)
        #pragma unroll
        for (int j = 0; j < 4; j++)
            t[ty + 8 * j][tx] = W[(size_t)(y0 + ty + 8 * j) * D_HID + x0 + tx];
        __syncthreads();
        #pragma unroll
        for (int j = 0; j < 4; j++) {
            int rr = ty + 8 * j;
            float v = t[tx][rr];
            __nv_bfloat16 hv = __float2bfloat16_rn(v);
            __nv_bfloat16 lv = __float2bfloat16_rn(v - __bfloat162float(hv));
            size_t o = (size_t)(x0 + rr) * D_HID + y0 + tx;
            h[o] = hv;
            l[o] = lv;
        }
    } else if (blk < 16384) {
        // RoPE tables
        int idx = ((blk - 12288) << 8) | tid;       // over SEQ*512
        int s = idx >> 9;
        int j = idx & 511;
        float inv = expf(-(float)j * (9.210340371976184f / 512.0f));
        float arg = (float)s * inv;
        float sv, cv;
        sincosf(arg, &sv, &cv);
        g_cos[idx] = cv;
        g_sin[idx] = sv;
    } else {
        // pack kv bias
        int i = ((blk - 16384) << 8) | tid;         // 0..2047
        g_bkv[i] = (i < D_HID) ? bk[i] : bv[i - D_HID];
    }
}

// ---------------------------------------------------------------------------
// bf16 3-term split GEMM: C[M,N] = A @ W + bias   (N = ldc = gridDim.x*128)
//   CTA tile 256x128, 8 warps of 64x64, K-chunk 32, 4-stage cp.async.
// ---------------------------------------------------------------------------
#define KC 32
#define NSTAGE 4
#define PLANE_A 16384                    // 256 rows * 64B
#define PLANE_B 8192                     // 128 rows * 64B
#define STAGE_BYTES (2*PLANE_A + 2*PLANE_B)  // 49152
#define GEMM_SMEM (NSTAGE*STAGE_BYTES)       // 196608
#define NCHUNK (D_HID/KC)                // 32

#define LDSM4(r0,r1,r2,r3,addr) \
    asm volatile("ldmatrix.sync.aligned.m8n8.x4.shared.b16 {%0,%1,%2,%3}, [%4];" \
        : "=r"(r0), "=r"(r1), "=r"(r2), "=r"(r3) : "r"(addr))

#define MMA_BF16(d, a, b0v, b1v) \
    asm volatile("mma.sync.aligned.m16n8k16.row.col.f32.bf16.bf16.f32 " \
        "{%0,%1,%2,%3}, {%4,%5,%6,%7}, {%8,%9}, {%0,%1,%2,%3};" \
        : "+f"((d)[0]), "+f"((d)[1]), "+f"((d)[2]), "+f"((d)[3]) \
        : "r"((a)[0]), "r"((a)[1]), "r"((a)[2]), "r"((a)[3]), "r"(b0v), "r"(b1v))

__global__ __launch_bounds__(256, 1)
void gemm_bf16_split(const __nv_bfloat16* __restrict__ Ah,
                     const __nv_bfloat16* __restrict__ Al,
                     const __nv_bfloat16* __restrict__ Bh,
                     const __nv_bfloat16* __restrict__ Bl,
                     const float* __restrict__ bias, float* __restrict__ C,
                     int ldc)
{
    extern __shared__ char smem[];
    uint32_t sb = smem_u32(smem);
    int tid = threadIdx.x, lane = tid & 31, wid = tid >> 5;
    int wm = (wid & 3) * 64;        // warp M offset (4 warps over 256)
    int wn = (wid >> 2) * 64;       // warp N offset (2 warps over 128)

    int mbaseA = blockIdx.y * 256;
    int nbaseB = blockIdx.x * 128;

    // loader mapping
    int lrow = tid >> 1;            // 0..127
    int lb0  = (tid & 1) * 2;       // 16B block pair

    // ldmatrix lane address precompute
    uint32_t aOff[4]; int aSw[4];
    #pragma unroll
    for (int mt = 0; mt < 4; mt++) {
        int r = wm + mt * 16 + (lane & 7) + ((lane >> 3) & 1) * 8;
        aOff[mt] = r * 64;
        aSw[mt] = (r >> 1) & 3;
    }
    int g = lane >> 3;
    uint32_t bOff[4]; int bSw[4];
    #pragma unroll
    for (int pk = 0; pk < 4; pk++) {
        int r = wn + pk * 16 + ((g >> 1) << 3) + (lane & 7);
        bOff[pk] = r * 64;
        bSw[pk] = (r >> 1) & 3;
    }
    int aKb = lane >> 4;
    int bKb = g & 1;

    float acc[4][8][4];
    #pragma unroll
    for (int i = 0; i < 4; i++)
        #pragma unroll
        for (int j = 0; j < 8; j++)
            #pragma unroll
            for (int c = 0; c < 4; c++) acc[i][j][c] = 0.0f;

    #define LOAD_CHUNK(chunk, stage) do {                                        \
        uint32_t st0 = sb + (stage) * STAGE_BYTES;                               \
        int kk = (chunk) * KC;                                                   \
        _Pragma("unroll")                                                        \
        for (int rr = 0; rr < 2; rr++) {                                         \
            int r = lrow + rr * 128;                                             \
            int sw = (r >> 1) & 3;                                               \
            const __nv_bfloat16* sh = Ah + (size_t)(mbaseA + r) * D_HID + kk;    \
            const __nv_bfloat16* sl = Al + (size_t)(mbaseA + r) * D_HID + kk;    \
            _Pragma("unroll")                                                    \
            for (int j = 0; j < 2; j++) {                                        \
                int blk = lb0 + j;                                               \
                uint32_t d = st0 + r * 64 + ((blk ^ sw) << 4);                   \
                asm volatile("cp.async.cg.shared.global [%0], [%1], 16;"         \
                             :: "r"(d), "l"(sh + blk * 8));                      \
                asm volatile("cp.async.cg.shared.global [%0], [%1], 16;"         \
                             :: "r"(d + PLANE_A), "l"(sl + blk * 8));            \
            }                                                                    \
        }                                                                        \
        {                                                                        \
            int r = lrow;                                                        \
            int sw = (r >> 1) & 3;                                               \
            const __nv_bfloat16* sh = Bh + (size_t)(nbaseB + r) * D_HID + kk;    \
            const __nv_bfloat16* sl = Bl + (size_t)(nbaseB + r) * D_HID + kk;    \
            _Pragma("unroll")                                                    \
            for (int j = 0; j < 2; j++) {                                        \
                int blk = lb0 + j;                                               \
                uint32_t d = st0 + 2 * PLANE_A + r * 64 + ((blk ^ sw) << 4);     \
                asm volatile("cp.async.cg.shared.global [%0], [%1], 16;"         \
                             :: "r"(d), "l"(sh + blk * 8));                      \
                asm volatile("cp.async.cg.shared.global [%0], [%1], 16;"         \
                             :: "r"(d + PLANE_B), "l"(sl + blk * 8));            \
            }                                                                    \
        }                                                                        \
    } while (0)

    #pragma unroll
    for (int s = 0; s < NSTAGE - 1; s++) {
        LOAD_CHUNK(s, s);
        asm volatile("cp.async.commit_group;");
    }

    for (int i = 0; i < NCHUNK; i++) {
        asm volatile("cp.async.wait_group %0;" :: "n"(NSTAGE - 2));
        __syncthreads();

        if (i + NSTAGE - 1 < NCHUNK)
            LOAD_CHUNK(i + NSTAGE - 1, (i + NSTAGE - 1) & (NSTAGE - 1));
        asm volatile("cp.async.commit_group;");

        uint32_t st = sb + (i & (NSTAGE - 1)) * STAGE_BYTES;
        #pragma unroll
        for (int s = 0; s < 2; s++) {
            uint32_t bh[16], bl[16];
            #pragma unroll
            for (int pk = 0; pk < 4; pk++) {
                uint32_t ad = st + 2 * PLANE_A + bOff[pk]
                            + (((2 * s + bKb) ^ bSw[pk]) << 4);
                LDSM4(bh[pk*4+0], bh[pk*4+1], bh[pk*4+2], bh[pk*4+3], ad);
                LDSM4(bl[pk*4+0], bl[pk*4+1], bl[pk*4+2], bl[pk*4+3], ad + PLANE_B);
            }
            uint32_t ah[4][4], al[4][4];
            #pragma unroll
            for (int mt = 0; mt < 4; mt++) {
                uint32_t ad = st + aOff[mt] + (((2 * s + aKb) ^ aSw[mt]) << 4);
                LDSM4(ah[mt][0], ah[mt][1], ah[mt][2], ah[mt][3], ad);
                LDSM4(al[mt][0], al[mt][1], al[mt][2], al[mt][3], ad + PLANE_A);
            }
            #pragma unroll
            for (int mt = 0; mt < 4; mt++)
                #pragma unroll
                for (int nt = 0; nt < 8; nt++)
                    MMA_BF16(acc[mt][nt], ah[mt], bh[nt*2], bh[nt*2+1]);
            #pragma unroll
            for (int mt = 0; mt < 4; mt++)
                #pragma unroll
                for (int nt = 0; nt < 8; nt++)
                    MMA_BF16(acc[mt][nt], ah[mt], bl[nt*2], bl[nt*2+1]);
            #pragma unroll
            for (int mt = 0; mt < 4; mt++)
                #pragma unroll
                for (int nt = 0; nt < 8; nt++)
                    MMA_BF16(acc[mt][nt], al[mt], bh[nt*2], bh[nt*2+1]);
        }
    }

    // epilogue
    #pragma unroll
    for (int mt = 0; mt < 4; mt++) {
        int row0 = blockIdx.y * 256 + wm + mt * 16 + (lane >> 2);
        #pragma unroll
        for (int nt = 0; nt < 8; nt++) {
            int col = blockIdx.x * 128 + wn + nt * 8 + (lane & 3) * 2;
            float b0 = bias[col], b1 = bias[col + 1];
            float2 v0, v1;
            v0.x = acc[mt][nt][0] + b0; v0.y = acc[mt][nt][1] + b1;
            v1.x = acc[mt][nt][2] + b0; v1.y = acc[mt][nt][3] + b1;
            *(float2*)(C + (size_t)row0 * ldc + col) = v0;
            *(float2*)(C + (size_t)(row0 + 8) * ldc + col) = v1;
        }
    }
}

// ---------------------------------------------------------------------------
// Fused: RoPE(q,k) + per-token head attention (16x16) + attn output +
// scrambled ctx written directly as bf16 hi/lo planes.
//   xs[b, h*128 + s/16, (s%16)*64 + d] = ctx[b, s, h, d]
// k/v come packed from g_kv (row stride 2048: k at +0, v at +1024).
// ---------------------------------------------------------------------------
__global__ __launch_bounds__(256) void attn_fused_kernel(float* __restrict__ attn_out,
                                                         int write_attn)
{
    __shared__ float sq[16][65];
    __shared__ float sk[16][65];
    __shared__ float sv[16][65];
    __shared__ float sc[16][17];

    int token = blockIdx.x;
    int tid   = threadIdx.x;
    int s     = token & (SEQ - 1);
    int b     = token >> 11;

    const float* qrow = g_q  + (size_t)token * D_HID;
    const float* krow = g_kv + (size_t)token * (2 * D_HID);
    const float* vrow = krow + D_HID;

    for (int i = tid; i < D_HID; i += 256) {
        int j  = i & 511;
        float c  = g_cos[(s << 9) | j];
        float sn = g_sin[(s << 9) | j];
        float qa = qrow[i], qb = qrow[i ^ 512];
        float ka = krow[i], kb = krow[i ^ 512];
        float rq, rk;
        if (i < 512) { rq = qa * c - qb * sn; rk = ka * c - kb * sn; }
        else         { rq = qa * c + qb * sn; rk = ka * c + kb * sn; }
        sq[i >> 6][i & 63] = rq;
        sk[i >> 6][i & 63] = rk;
        sv[i >> 6][i & 63] = vrow[i];
    }
    __syncthreads();

    {
        int h = tid >> 4, t = tid & 15;
        float acc = 0.0f;
        #pragma unroll
        for (int d = 0; d < HD; d++)
            acc = fmaf(sq[h][d], sk[t][d], acc);
        sc[h][t] = acc * 0.125f;
    }
    __syncthreads();

    if (tid < 16) {
        float m = -1e30f;
        #pragma unroll
        for (int t = 0; t < 16; t++) m = fmaxf(m, sc[tid][t]);
        float sum = 0.0f;
        #pragma unroll
        for (int t = 0; t < 16; t++) {
            float e = expf(sc[tid][t] - m);
            sc[tid][t] = e;
            sum += e;
        }
        float r = 1.0f / sum;
        #pragma unroll
        for (int t = 0; t < 16; t++) sc[tid][t] *= r;
    }
    __syncthreads();

    if (write_attn)
        attn_out[(size_t)token * 256 + tid] = sc[tid >> 4][tid & 15];

    // ctx + scrambled bf16 split write
    int o0 = tid * 4;
    int h  = o0 >> 6;
    int d0 = o0 & 63;
    size_t xbase = ((size_t)b * SEQ + (h * 128 + (s >> 4))) * D_HID
                 + ((s & 15) << 6);
    __nv_bfloat16* xh = g_xs_h + xbase;
    __nv_bfloat16* xl = g_xs_l + xbase;
    #pragma unroll
    for (int jj = 0; jj < 4; jj++) {
        int d = d0 + jj;
        float acc = 0.0f;
        #pragma unroll
        for (int t = 0; t < 16; t++)
            acc = fmaf(sc[h][t], sv[t][d], acc);
        __nv_bfloat16 hv = __float2bfloat16_rn(acc);
        __nv_bfloat16 lv = __float2bfloat16_rn(acc - __bfloat162float(hv));
        xh[d] = hv;
        xl[d] = lv;
    }
}

// ---------------------------------------------------------------------------
extern "C" void kernel_launch(void* const* d_in, const int* in_sizes, int n_in,
                              void* d_out, int out_size)
{
    const float* inputs  = (const float*)d_in[0];
    const float* context = (const float*)d_in[1];
    const float* Wq = (const float*)d_in[2];
    const float* bq = (const float*)d_in[3];
    const float* Wk = (const float*)d_in[4];
    const float* bk = (const float*)d_in[5];
    const float* Wv = (const float*)d_in[6];
    const float* bv = (const float*)d_in[7];
    const float* Wo = (const float*)d_in[8];
    const float* bo = (const float*)d_in[9];
    float* out = (float*)d_out;

    float *q, *kv, *bkv;
    __nv_bfloat16 *inh, *inl, *cxh, *cxl, *xsh, *xsl, *wth, *wtl;
    cudaGetSymbolAddress((void**)&q,   g_q);
    cudaGetSymbolAddress((void**)&kv,  g_kv);
    cudaGetSymbolAddress((void**)&bkv, g_bkv);
    cudaGetSymbolAddress((void**)&inh, g_in_h);
    cudaGetSymbolAddress((void**)&inl, g_in_l);
    cudaGetSymbolAddress((void**)&cxh, g_cx_h);
    cudaGetSymbolAddress((void**)&cxl, g_cx_l);
    cudaGetSymbolAddress((void**)&xsh, g_xs_h);
    cudaGetSymbolAddress((void**)&xsl, g_xs_l);
    cudaGetSymbolAddress((void**)&wth, g_wt_h);
    cudaGetSymbolAddress((void**)&wtl, g_wt_l);

    cudaFuncSetAttribute(gemm_bf16_split,
                         cudaFuncAttributeMaxDynamicSharedMemorySize, GEMM_SMEM);

    const size_t WSZ = (size_t)D_HID * D_HID;

    // 1) fused prep: tables + activation splits + weight transpose/split + bias pack
    prep_kernel<<<16392, 256>>>(inputs, context, Wq, Wk, Wv, Wo, bk, bv);

    // 2) Q projection (N=1024)
    {
        dim3 g(8, 16);
        gemm_bf16_split<<<g, 256, GEMM_SMEM>>>(inh, inl, wth + 0*WSZ, wtl + 0*WSZ,
                                               bq, q, D_HID);
    }
    // 3) K+V merged projection (N=2048, Wk|Wv planes contiguous)
    {
        dim3 g(16, 16);
        gemm_bf16_split<<<g, 256, GEMM_SMEM>>>(cxh, cxl, wth + 1*WSZ, wtl + 1*WSZ,
                                               bkv, kv, 2 * D_HID);
    }

    // 4) fused RoPE + head-attention + scrambled bf16 ctx
    int write_attn = (out_size >= OUT_MAIN + ATTN_ELEMS) ? 1 : 0;
    attn_fused_kernel<<<MROWS, 256>>>(out + OUT_MAIN, write_attn);

    // 5) final projection
    {
        dim3 g(8, 16);
        gemm_bf16_split<<<g, 256, GEMM_SMEM>>>(xsh, xsl, wth + 3*WSZ, wtl + 3*WSZ,
                                               bo, out, D_HID);
    }
}

// round 9
// speedup vs baseline: 2.4943x; 1.0387x over previous
#include <cuda_runtime.h>
#include <cuda_bf16.h>
#include <math.h>
#include <stdint.h>

// Shapes (fixed)
#define D_HID 1024
#define SEQ   2048
#define BATCH 2
#define HEADS 16
#define HD    64
#define MROWS (BATCH*SEQ)                 // 4096
#define OUT_MAIN (MROWS*D_HID)            // 4194304
#define ATTN_ELEMS (MROWS*HEADS*HEADS)    // 1048576

// fp32 scratch
__device__ float g_q [MROWS*D_HID];
__device__ float g_kv[MROWS*2*D_HID];     // packed rows: k[0..1023] | v[1024..2047]
__device__ float g_bkv[2*D_HID];          // bk || bv
__device__ float g_cos[SEQ*(D_HID/2)];
__device__ float g_sin[SEQ*(D_HID/2)];

// bf16 split planes
__device__ __nv_bfloat16 g_in_h[MROWS*D_HID];
__device__ __nv_bfloat16 g_in_l[MROWS*D_HID];
__device__ __nv_bfloat16 g_cx_h[MROWS*D_HID];
__device__ __nv_bfloat16 g_cx_l[MROWS*D_HID];
__device__ __nv_bfloat16 g_xs_h[MROWS*D_HID];
__device__ __nv_bfloat16 g_xs_l[MROWS*D_HID];
__device__ __nv_bfloat16 g_wt_h[4*D_HID*D_HID];   // W^T hi (Wq,Wk,Wv,Wo)
__device__ __nv_bfloat16 g_wt_l[4*D_HID*D_HID];   // W^T lo

__device__ __forceinline__ uint32_t smem_u32(const void* p) {
    uint32_t a;
    asm("{ .reg .u64 t; cvta.to.shared.u64 t, %1; cvt.u32.u64 %0, t; }"
        : "=r"(a) : "l"(p));
    return a;
}

// ---------------------------------------------------------------------------
// Fused prep kernel (unchanged from R8)
// ---------------------------------------------------------------------------
__global__ __launch_bounds__(256)
void prep_kernel(const float* __restrict__ inputs, const float* __restrict__ context,
                 const float* __restrict__ W0, const float* __restrict__ W1,
                 const float* __restrict__ W2, const float* __restrict__ W3,
                 const float* __restrict__ bk, const float* __restrict__ bv)
{
    int blk = blockIdx.x;
    int tid = threadIdx.x;

    if (blk < 8192) {
        int which = blk >> 12;
        int idx = ((blk & 4095) << 8) | tid;
        const float4* src = (const float4*)(which ? context : inputs);
        uint2* h = (uint2*)(which ? g_cx_h : g_in_h);
        uint2* l = (uint2*)(which ? g_cx_l : g_in_l);
        float4 v = src[idx];
        __nv_bfloat16 hx = __float2bfloat16_rn(v.x);
        __nv_bfloat16 hy = __float2bfloat16_rn(v.y);
        __nv_bfloat16 hz = __float2bfloat16_rn(v.z);
        __nv_bfloat16 hw = __float2bfloat16_rn(v.w);
        __nv_bfloat16 lx = __float2bfloat16_rn(v.x - __bfloat162float(hx));
        __nv_bfloat16 ly = __float2bfloat16_rn(v.y - __bfloat162float(hy));
        __nv_bfloat16 lz = __float2bfloat16_rn(v.z - __bfloat162float(hz));
        __nv_bfloat16 lw = __float2bfloat16_rn(v.w - __bfloat162float(hw));
        __nv_bfloat162 h01; h01.x = hx; h01.y = hy;
        __nv_bfloat162 h23; h23.x = hz; h23.y = hw;
        __nv_bfloat162 l01; l01.x = lx; l01.y = ly;
        __nv_bfloat162 l23; l23.x = lz; l23.y = lw;
        uint2 uh, ul;
        uh.x = *(uint32_t*)&h01; uh.y = *(uint32_t*)&h23;
        ul.x = *(uint32_t*)&l01; ul.y = *(uint32_t*)&l23;
        h[idx] = uh;
        l[idx] = ul;
    } else if (blk < 12288) {
        __shared__ float t[32][33];
        int r  = blk - 8192;
        int z  = r >> 10;
        int bi = r & 1023;
        int x0 = (bi & 31) * 32;
        int y0 = (bi >> 5) * 32;
        const float* W = (z == 0) ? W0 : (z == 1) ? W1 : (z == 2) ? W2 : W3;
        __nv_bfloat16* h = g_wt_h + (size_t)z * D_HID * D_HID;
        __nv_bfloat16* l = g_wt_l + (size_t)z * D_HID * D_HID;
        int tx = tid & 31, ty = tid >> 5;
        #pragma unroll
        for (int j = 0; j < 4; j++)
            t[ty + 8 * j][tx] = W[(size_t)(y0 + ty + 8 * j) * D_HID + x0 + tx];
        __syncthreads();
        #pragma unroll
        for (int j = 0; j < 4; j++) {
            int rr = ty + 8 * j;
            float v = t[tx][rr];
            __nv_bfloat16 hv = __float2bfloat16_rn(v);
            __nv_bfloat16 lv = __float2bfloat16_rn(v - __bfloat162float(hv));
            size_t o = (size_t)(x0 + rr) * D_HID + y0 + tx;
            h[o] = hv;
            l[o] = lv;
        }
    } else if (blk < 16384) {
        int idx = ((blk - 12288) << 8) | tid;
        int s = idx >> 9;
        int j = idx & 511;
        float inv = expf(-(float)j * (9.210340371976184f / 512.0f));
        float arg = (float)s * inv;
        float sv, cv;
        sincosf(arg, &sv, &cv);
        g_cos[idx] = cv;
        g_sin[idx] = sv;
    } else {
        int i = ((blk - 16384) << 8) | tid;
        g_bkv[i] = (i < D_HID) ? bk[i] : bv[i - D_HID];
    }
}

// ---------------------------------------------------------------------------
// bf16 3-term split GEMM (unchanged from R8)
// ---------------------------------------------------------------------------
#define KC 32
#define NSTAGE 4
#define PLANE_A 16384
#define PLANE_B 8192
#define STAGE_BYTES (2*PLANE_A + 2*PLANE_B)
#define GEMM_SMEM (NSTAGE*STAGE_BYTES)
#define NCHUNK (D_HID/KC)

#define LDSM4(r0,r1,r2,r3,addr) \
    asm volatile("ldmatrix.sync.aligned.m8n8.x4.shared.b16 {%0,%1,%2,%3}, [%4];" \
        : "=r"(r0), "=r"(r1), "=r"(r2), "=r"(r3) : "r"(addr))

#define MMA_BF16(d, a, b0v, b1v) \
    asm volatile("mma.sync.aligned.m16n8k16.row.col.f32.bf16.bf16.f32 " \
        "{%0,%1,%2,%3}, {%4,%5,%6,%7}, {%8,%9}, {%0,%1,%2,%3};" \
        : "+f"((d)[0]), "+f"((d)[1]), "+f"((d)[2]), "+f"((d)[3]) \
        : "r"((a)[0]), "r"((a)[1]), "r"((a)[2]), "r"((a)[3]), "r"(b0v), "r"(b1v))

__global__ __launch_bounds__(256, 1)
void gemm_bf16_split(const __nv_bfloat16* __restrict__ Ah,
                     const __nv_bfloat16* __restrict__ Al,
                     const __nv_bfloat16* __restrict__ Bh,
                     const __nv_bfloat16* __restrict__ Bl,
                     const float* __restrict__ bias, float* __restrict__ C,
                     int ldc)
{
    extern __shared__ char smem[];
    uint32_t sb = smem_u32(smem);
    int tid = threadIdx.x, lane = tid & 31, wid = tid >> 5;
    int wm = (wid & 3) * 64;
    int wn = (wid >> 2) * 64;

    int mbaseA = blockIdx.y * 256;
    int nbaseB = blockIdx.x * 128;

    int lrow = tid >> 1;
    int lb0  = (tid & 1) * 2;

    uint32_t aOff[4]; int aSw[4];
    #pragma unroll
    for (int mt = 0; mt < 4; mt++) {
        int r = wm + mt * 16 + (lane & 7) + ((lane >> 3) & 1) * 8;
        aOff[mt] = r * 64;
        aSw[mt] = (r >> 1) & 3;
    }
    int g = lane >> 3;
    uint32_t bOff[4]; int bSw[4];
    #pragma unroll
    for (int pk = 0; pk < 4; pk++) {
        int r = wn + pk * 16 + ((g >> 1) << 3) + (lane & 7);
        bOff[pk] = r * 64;
        bSw[pk] = (r >> 1) & 3;
    }
    int aKb = lane >> 4;
    int bKb = g & 1;

    float acc[4][8][4];
    #pragma unroll
    for (int i = 0; i < 4; i++)
        #pragma unroll
        for (int j = 0; j < 8; j++)
            #pragma unroll
            for (int c = 0; c < 4; c++) acc[i][j][c] = 0.0f;

    #define LOAD_CHUNK(chunk, stage) do {                                        \
        uint32_t st0 = sb + (stage) * STAGE_BYTES;                               \
        int kk = (chunk) * KC;                                                   \
        _Pragma("unroll")                                                        \
        for (int rr = 0; rr < 2; rr++) {                                         \
            int r = lrow + rr * 128;                                             \
            int sw = (r >> 1) & 3;                                               \
            const __nv_bfloat16* sh = Ah + (size_t)(mbaseA + r) * D_HID + kk;    \
            const __nv_bfloat16* sl = Al + (size_t)(mbaseA + r) * D_HID + kk;    \
            _Pragma("unroll")                                                    \
            for (int j = 0; j < 2; j++) {                                        \
                int blk = lb0 + j;                                               \
                uint32_t d = st0 + r * 64 + ((blk ^ sw) << 4);                   \
                asm volatile("cp.async.cg.shared.global [%0], [%1], 16;"         \
                             :: "r"(d), "l"(sh + blk * 8));                      \
                asm volatile("cp.async.cg.shared.global [%0], [%1], 16;"         \
                             :: "r"(d + PLANE_A), "l"(sl + blk * 8));            \
            }                                                                    \
        }                                                                        \
        {                                                                        \
            int r = lrow;                                                        \
            int sw = (r >> 1) & 3;                                               \
            const __nv_bfloat16* sh = Bh + (size_t)(nbaseB + r) * D_HID + kk;    \
            const __nv_bfloat16* sl = Bl + (size_t)(nbaseB + r) * D_HID + kk;    \
            _Pragma("unroll")                                                    \
            for (int j = 0; j < 2; j++) {                                        \
                int blk = lb0 + j;                                               \
                uint32_t d = st0 + 2 * PLANE_A + r * 64 + ((blk ^ sw) << 4);     \
                asm volatile("cp.async.cg.shared.global [%0], [%1], 16;"         \
                             :: "r"(d), "l"(sh + blk * 8));                      \
                asm volatile("cp.async.cg.shared.global [%0], [%1], 16;"         \
                             :: "r"(d + PLANE_B), "l"(sl + blk * 8));            \
            }                                                                    \
        }                                                                        \
    } while (0)

    #pragma unroll
    for (int s = 0; s < NSTAGE - 1; s++) {
        LOAD_CHUNK(s, s);
        asm volatile("cp.async.commit_group;");
    }

    for (int i = 0; i < NCHUNK; i++) {
        asm volatile("cp.async.wait_group %0;" :: "n"(NSTAGE - 2));
        __syncthreads();

        if (i + NSTAGE - 1 < NCHUNK)
            LOAD_CHUNK(i + NSTAGE - 1, (i + NSTAGE - 1) & (NSTAGE - 1));
        asm volatile("cp.async.commit_group;");

        uint32_t st = sb + (i & (NSTAGE - 1)) * STAGE_BYTES;
        #pragma unroll
        for (int s = 0; s < 2; s++) {
            uint32_t bh[16], bl[16];
            #pragma unroll
            for (int pk = 0; pk < 4; pk++) {
                uint32_t ad = st + 2 * PLANE_A + bOff[pk]
                            + (((2 * s + bKb) ^ bSw[pk]) << 4);
                LDSM4(bh[pk*4+0], bh[pk*4+1], bh[pk*4+2], bh[pk*4+3], ad);
                LDSM4(bl[pk*4+0], bl[pk*4+1], bl[pk*4+2], bl[pk*4+3], ad + PLANE_B);
            }
            uint32_t ah[4][4], al[4][4];
            #pragma unroll
            for (int mt = 0; mt < 4; mt++) {
                uint32_t ad = st + aOff[mt] + (((2 * s + aKb) ^ aSw[mt]) << 4);
                LDSM4(ah[mt][0], ah[mt][1], ah[mt][2], ah[mt][3], ad);
                LDSM4(al[mt][0], al[mt][1], al[mt][2], al[mt][3], ad + PLANE_A);
            }
            #pragma unroll
            for (int mt = 0; mt < 4; mt++)
                #pragma unroll
                for (int nt = 0; nt < 8; nt++)
                    MMA_BF16(acc[mt][nt], ah[mt], bh[nt*2], bh[nt*2+1]);
            #pragma unroll
            for (int mt = 0; mt < 4; mt++)
                #pragma unroll
                for (int nt = 0; nt < 8; nt++)
                    MMA_BF16(acc[mt][nt], ah[mt], bl[nt*2], bl[nt*2+1]);
            #pragma unroll
            for (int mt = 0; mt < 4; mt++)
                #pragma unroll
                for (int nt = 0; nt < 8; nt++)
                    MMA_BF16(acc[mt][nt], al[mt], bh[nt*2], bh[nt*2+1]);
        }
    }

    #pragma unroll
    for (int mt = 0; mt < 4; mt++) {
        int row0 = blockIdx.y * 256 + wm + mt * 16 + (lane >> 2);
        #pragma unroll
        for (int nt = 0; nt < 8; nt++) {
            int col = blockIdx.x * 128 + wn + nt * 8 + (lane & 3) * 2;
            float b0 = bias[col], b1 = bias[col + 1];
            float2 v0, v1;
            v0.x = acc[mt][nt][0] + b0; v0.y = acc[mt][nt][1] + b1;
            v1.x = acc[mt][nt][2] + b0; v1.y = acc[mt][nt][3] + b1;
            *(float2*)(C + (size_t)row0 * ldc + col) = v0;
            *(float2*)(C + (size_t)(row0 + 8) * ldc + col) = v1;
        }
    }
}

// ---------------------------------------------------------------------------
// Vectorized fused attention: RoPE(q,k) + head attention (16x16) + attn out +
// scrambled bf16 ctx. Everything float4; softmax via width-16 shuffles.
//   smem rows padded to 68 floats (float4-aligned, conflict-free patterns).
// ---------------------------------------------------------------------------
#define SROW 68

__global__ __launch_bounds__(256) void attn_fused_kernel(float* __restrict__ attn_out,
                                                         int write_attn)
{
    __shared__ float sq[16 * SROW];
    __shared__ float sk[16 * SROW];
    __shared__ float sv[16 * SROW];
    __shared__ float sc[16][17];

    int token = blockIdx.x;
    int tid   = threadIdx.x;
    int s     = token & (SEQ - 1);
    int b     = token >> 11;

    const float4* qrow = (const float4*)(g_q  + (size_t)token * D_HID);
    const float4* krow = (const float4*)(g_kv + (size_t)token * (2 * D_HID));
    const float4* vrow = krow + (D_HID / 4);

    // ---- load + RoPE (1 float4 per tensor per thread) ----
    {
        int i0 = tid * 4;                         // element index 0..1023
        int j0 = i0 & 511;
        const float4* cs = (const float4*)(g_cos + (s << 9) + j0);
        const float4* sn = (const float4*)(g_sin + (s << 9) + j0);
        float4 c4 = cs[0], s4 = sn[0];
        float4 qv = qrow[tid], qp = qrow[tid ^ 128];
        float4 kv = krow[tid], kp = krow[tid ^ 128];
        float sgn = (i0 < 512) ? -1.0f : 1.0f;
        float4 rq, rk;
        rq.x = qv.x * c4.x + sgn * qp.x * s4.x;
        rq.y = qv.y * c4.y + sgn * qp.y * s4.y;
        rq.z = qv.z * c4.z + sgn * qp.z * s4.z;
        rq.w = qv.w * c4.w + sgn * qp.w * s4.w;
        rk.x = kv.x * c4.x + sgn * kp.x * s4.x;
        rk.y = kv.y * c4.y + sgn * kp.y * s4.y;
        rk.z = kv.z * c4.z + sgn * kp.z * s4.z;
        rk.w = kv.w * c4.w + sgn * kp.w * s4.w;
        int row = tid >> 4;                       // i0 >> 6
        int c4i = tid & 15;                       // (i0 & 63) / 4
        *(float4*)(sq + row * SROW + c4i * 4) = rq;
        *(float4*)(sk + row * SROW + c4i * 4) = rk;
        *(float4*)(sv + row * SROW + c4i * 4) = vrow[tid];
    }
    __syncthreads();

    // ---- scores + softmax: thread (h, t) ----
    int h = tid >> 4, t = tid & 15;
    {
        const float4* q4 = (const float4*)(sq + h * SROW);
        const float4* k4 = (const float4*)(sk + t * SROW);
        float ax = 0.0f, ay = 0.0f, az = 0.0f, aw = 0.0f;
        #pragma unroll
        for (int dd = 0; dd < 16; dd++) {
            float4 a = q4[dd], bb = k4[dd];
            ax = fmaf(a.x, bb.x, ax);
            ay = fmaf(a.y, bb.y, ay);
            az = fmaf(a.z, bb.z, az);
            aw = fmaf(a.w, bb.w, aw);
        }
        float sco = (ax + ay + az + aw) * 0.125f;

        // width-16 softmax (lanes of same h within warp)
        float m = sco;
        #pragma unroll
        for (int o = 8; o; o >>= 1)
            m = fmaxf(m, __shfl_xor_sync(0xffffffffu, m, o));
        float e = expf(sco - m);
        float sum = e;
        #pragma unroll
        for (int o = 8; o; o >>= 1)
            sum += __shfl_xor_sync(0xffffffffu, sum, o);
        float p = e / sum;
        sc[h][t] = p;
        if (write_attn)
            attn_out[(size_t)token * 256 + tid] = p;
    }
    __syncthreads();

    // ---- ctx + scrambled bf16 split write: thread (h, d4) ----
    {
        int d4 = tid & 15;                        // float4 index within head dim
        const float4* v4 = (const float4*)(sv) + d4;  // row stride SROW/4 = 17
        float4 acc = make_float4(0.0f, 0.0f, 0.0f, 0.0f);
        #pragma unroll
        for (int tt = 0; tt < 16; tt++) {
            float p = sc[h][tt];
            float4 vv = v4[tt * (SROW / 4)];
            acc.x = fmaf(p, vv.x, acc.x);
            acc.y = fmaf(p, vv.y, acc.y);
            acc.z = fmaf(p, vv.z, acc.z);
            acc.w = fmaf(p, vv.w, acc.w);
        }
        size_t xbase = ((size_t)b * SEQ + (h * 128 + (s >> 4))) * D_HID
                     + ((s & 15) << 6) + d4 * 4;
        __nv_bfloat16 h0 = __float2bfloat16_rn(acc.x);
        __nv_bfloat16 h1 = __float2bfloat16_rn(acc.y);
        __nv_bfloat16 h2 = __float2bfloat16_rn(acc.z);
        __nv_bfloat16 h3 = __float2bfloat16_rn(acc.w);
        __nv_bfloat16 l0 = __float2bfloat16_rn(acc.x - __bfloat162float(h0));
        __nv_bfloat16 l1 = __float2bfloat16_rn(acc.y - __bfloat162float(h1));
        __nv_bfloat16 l2 = __float2bfloat16_rn(acc.z - __bfloat162float(h2));
        __nv_bfloat16 l3 = __float2bfloat16_rn(acc.w - __bfloat162float(h3));
        __nv_bfloat162 hp0; hp0.x = h0; hp0.y = h1;
        __nv_bfloat162 hp1; hp1.x = h2; hp1.y = h3;
        __nv_bfloat162 lp0; lp0.x = l0; lp0.y = l1;
        __nv_bfloat162 lp1; lp1.x = l2; lp1.y = l3;
        uint2 uh, ul;
        uh.x = *(uint32_t*)&hp0; uh.y = *(uint32_t*)&hp1;
        ul.x = *(uint32_t*)&lp0; ul.y = *(uint32_t*)&lp1;
        *(uint2*)(g_xs_h + xbase) = uh;
        *(uint2*)(g_xs_l + xbase) = ul;
    }
}

// ---------------------------------------------------------------------------
extern "C" void kernel_launch(void* const* d_in, const int* in_sizes, int n_in,
                              void* d_out, int out_size)
{
    const float* inputs  = (const float*)d_in[0];
    const float* context = (const float*)d_in[1];
    const float* Wq = (const float*)d_in[2];
    const float* bq = (const float*)d_in[3];
    const float* Wk = (const float*)d_in[4];
    const float* bk = (const float*)d_in[5];
    const float* Wv = (const float*)d_in[6];
    const float* bv = (const float*)d_in[7];
    const float* Wo = (const float*)d_in[8];
    const float* bo = (const float*)d_in[9];
    float* out = (float*)d_out;

    float *q, *kv, *bkv;
    __nv_bfloat16 *inh, *inl, *cxh, *cxl, *xsh, *xsl, *wth, *wtl;
    cudaGetSymbolAddress((void**)&q,   g_q);
    cudaGetSymbolAddress((void**)&kv,  g_kv);
    cudaGetSymbolAddress((void**)&bkv, g_bkv);
    cudaGetSymbolAddress((void**)&inh, g_in_h);
    cudaGetSymbolAddress((void**)&inl, g_in_l);
    cudaGetSymbolAddress((void**)&cxh, g_cx_h);
    cudaGetSymbolAddress((void**)&cxl, g_cx_l);
    cudaGetSymbolAddress((void**)&xsh, g_xs_h);
    cudaGetSymbolAddress((void**)&xsl, g_xs_l);
    cudaGetSymbolAddress((void**)&wth, g_wt_h);
    cudaGetSymbolAddress((void**)&wtl, g_wt_l);

    cudaFuncSetAttribute(gemm_bf16_split,
                         cudaFuncAttributeMaxDynamicSharedMemorySize, GEMM_SMEM);

    const size_t WSZ = (size_t)D_HID * D_HID;

    // 1) fused prep
    prep_kernel<<<16392, 256>>>(inputs, context, Wq, Wk, Wv, Wo, bk, bv);

    // 2) Q projection (N=1024)
    {
        dim3 g(8, 16);
        gemm_bf16_split<<<g, 256, GEMM_SMEM>>>(inh, inl, wth + 0*WSZ, wtl + 0*WSZ,
                                               bq, q, D_HID);
    }
    // 3) K+V merged projection (N=2048)
    {
        dim3 g(16, 16);
        gemm_bf16_split<<<g, 256, GEMM_SMEM>>>(cxh, cxl, wth + 1*WSZ, wtl + 1*WSZ,
                                               bkv, kv, 2 * D_HID);
    }

    // 4) fused vectorized RoPE + head-attention + scrambled bf16 ctx
    int write_attn = (out_size >= OUT_MAIN + ATTN_ELEMS) ? 1 : 0;
    attn_fused_kernel<<<MROWS, 256>>>(out + OUT_MAIN, write_attn);

    // 5) final projection
    {
        dim3 g(8, 16);
        gemm_bf16_split<<<g, 256, GEMM_SMEM>>>(xsh, xsl, wth + 3*WSZ, wtl + 3*WSZ,
                                               bo, out, D_HID);
    }
}

// round 10
// speedup vs baseline: 3.5939x; 1.4408x over previous
#include <cuda_runtime.h>
#include <cuda_fp16.h>
#include <math.h>
#include <stdint.h>

// Shapes (fixed)
#define D_HID 1024
#define SEQ   2048
#define BATCH 2
#define HEADS 16
#define HD    64
#define MROWS (BATCH*SEQ)                 // 4096
#define OUT_MAIN (MROWS*D_HID)            // 4194304
#define ATTN_ELEMS (MROWS*HEADS*HEADS)    // 1048576

// fp32 scratch
__device__ float g_q [MROWS*D_HID];
__device__ float g_kv[MROWS*2*D_HID];     // packed rows: k | v
__device__ float g_bkv[2*D_HID];          // bk || bv
__device__ float g_cos[SEQ*(D_HID/2)];
__device__ float g_sin[SEQ*(D_HID/2)];

// fp16 operand planes: activations single plane; weights hi+lo (exact to 2^-24)
__device__ __half g_in_h[MROWS*D_HID];
__device__ __half g_cx_h[MROWS*D_HID];
__device__ __half g_xs_h[MROWS*D_HID];
__device__ __half g_wt_h[4*D_HID*D_HID];  // W^T hi (Wq,Wk,Wv,Wo)
__device__ __half g_wt_l[4*D_HID*D_HID];  // W^T lo

__device__ __forceinline__ uint32_t smem_u32(const void* p) {
    uint32_t a;
    asm("{ .reg .u64 t; cvta.to.shared.u64 t, %1; cvt.u32.u64 %0, t; }"
        : "=r"(a) : "l"(p));
    return a;
}

// ---------------------------------------------------------------------------
// Fused prep kernel:
//   [0,8192)      : fp32 -> fp16 convert of inputs / context (single plane)
//   [8192,12288)  : W transpose + fp16 hi/lo split for 4 weights
//   [12288,16384) : RoPE tables
//   [16384,16392) : pack bk||bv
// ---------------------------------------------------------------------------
__global__ __launch_bounds__(256)
void prep_kernel(const float* __restrict__ inputs, const float* __restrict__ context,
                 const float* __restrict__ W0, const float* __restrict__ W1,
                 const float* __restrict__ W2, const float* __restrict__ W3,
                 const float* __restrict__ bk, const float* __restrict__ bv)
{
    int blk = blockIdx.x;
    int tid = threadIdx.x;

    if (blk < 8192) {
        int which = blk >> 12;
        int idx = ((blk & 4095) << 8) | tid;        // float4 index
        const float4* src = (const float4*)(which ? context : inputs);
        uint2* h = (uint2*)(which ? g_cx_h : g_in_h);
        float4 v = src[idx];
        __half2 p0 = __floats2half2_rn(v.x, v.y);
        __half2 p1 = __floats2half2_rn(v.z, v.w);
        uint2 u;
        u.x = *(uint32_t*)&p0;
        u.y = *(uint32_t*)&p1;
        h[idx] = u;
    } else if (blk < 12288) {
        __shared__ float t[32][33];
        int r  = blk - 8192;
        int z  = r >> 10;
        int bi = r & 1023;
        int x0 = (bi & 31) * 32;
        int y0 = (bi >> 5) * 32;
        const float* W = (z == 0) ? W0 : (z == 1) ? W1 : (z == 2) ? W2 : W3;
        __half* h = g_wt_h + (size_t)z * D_HID * D_HID;
        __half* l = g_wt_l + (size_t)z * D_HID * D_HID;
        int tx = tid & 31, ty = tid >> 5;
        #pragma unroll
        for (int j = 0; j < 4; j++)
            t[ty + 8 * j][tx] = W[(size_t)(y0 + ty + 8 * j) * D_HID + x0 + tx];
        __syncthreads();
        #pragma unroll
        for (int j = 0; j < 4; j++) {
            int rr = ty + 8 * j;
            float v = t[tx][rr];
            __half hv = __float2half_rn(v);
            __half lv = __float2half_rn(v - __half2float(hv));
            size_t o = (size_t)(x0 + rr) * D_HID + y0 + tx;
            h[o] = hv;
            l[o] = lv;
        }
    } else if (blk < 16384) {
        int idx = ((blk - 12288) << 8) | tid;
        int s = idx >> 9;
        int j = idx & 511;
        float inv = expf(-(float)j * (9.210340371976184f / 512.0f));
        float arg = (float)s * inv;
        float sv, cv;
        sincosf(arg, &sv, &cv);
        g_cos[idx] = cv;
        g_sin[idx] = sv;
    } else {
        int i = ((blk - 16384) << 8) | tid;
        g_bkv[i] = (i < D_HID) ? bk[i] : bv[i - D_HID];
    }
}

// ---------------------------------------------------------------------------
// fp16 2-term GEMM: C[M,N] = A_f16 @ (W_hi + W_lo) + bias
//   CTA 256x128, 8 warps of 64x64, K-chunk 32, 4-stage cp.async.
//   2 MMA passes per k16 slab: ah*bh, ah*bl (vs 3 in bf16 3-term).
// ---------------------------------------------------------------------------
#define KC 32
#define NSTAGE 4
#define PLANE_A 16384                    // 256 rows * 64B (single A plane)
#define PLANE_B 8192                     // 128 rows * 64B
#define STAGE_BYTES (PLANE_A + 2*PLANE_B)    // 32768
#define GEMM_SMEM (NSTAGE*STAGE_BYTES)       // 131072
#define NCHUNK (D_HID/KC)                // 32

#define LDSM4(r0,r1,r2,r3,addr) \
    asm volatile("ldmatrix.sync.aligned.m8n8.x4.shared.b16 {%0,%1,%2,%3}, [%4];" \
        : "=r"(r0), "=r"(r1), "=r"(r2), "=r"(r3) : "r"(addr))

#define MMA_F16(d, a, b0v, b1v) \
    asm volatile("mma.sync.aligned.m16n8k16.row.col.f32.f16.f16.f32 " \
        "{%0,%1,%2,%3}, {%4,%5,%6,%7}, {%8,%9}, {%0,%1,%2,%3};" \
        : "+f"((d)[0]), "+f"((d)[1]), "+f"((d)[2]), "+f"((d)[3]) \
        : "r"((a)[0]), "r"((a)[1]), "r"((a)[2]), "r"((a)[3]), "r"(b0v), "r"(b1v))

__global__ __launch_bounds__(256, 1)
void gemm_f16_2t(const __half* __restrict__ Ah,
                 const __half* __restrict__ Bh,
                 const __half* __restrict__ Bl,
                 const float* __restrict__ bias, float* __restrict__ C,
                 int ldc)
{
    extern __shared__ char smem[];
    uint32_t sb = smem_u32(smem);
    int tid = threadIdx.x, lane = tid & 31, wid = tid >> 5;
    int wm = (wid & 3) * 64;
    int wn = (wid >> 2) * 64;

    int mbaseA = blockIdx.y * 256;
    int nbaseB = blockIdx.x * 128;

    int lrow = tid >> 1;
    int lb0  = (tid & 1) * 2;

    uint32_t aOff[4]; int aSw[4];
    #pragma unroll
    for (int mt = 0; mt < 4; mt++) {
        int r = wm + mt * 16 + (lane & 7) + ((lane >> 3) & 1) * 8;
        aOff[mt] = r * 64;
        aSw[mt] = (r >> 1) & 3;
    }
    int g = lane >> 3;
    uint32_t bOff[4]; int bSw[4];
    #pragma unroll
    for (int pk = 0; pk < 4; pk++) {
        int r = wn + pk * 16 + ((g >> 1) << 3) + (lane & 7);
        bOff[pk] = r * 64;
        bSw[pk] = (r >> 1) & 3;
    }
    int aKb = lane >> 4;
    int bKb = g & 1;

    float acc[4][8][4];
    #pragma unroll
    for (int i = 0; i < 4; i++)
        #pragma unroll
        for (int j = 0; j < 8; j++)
            #pragma unroll
            for (int c = 0; c < 4; c++) acc[i][j][c] = 0.0f;

    #define LOAD_CHUNK(chunk, stage) do {                                        \
        uint32_t st0 = sb + (stage) * STAGE_BYTES;                               \
        int kk = (chunk) * KC;                                                   \
        _Pragma("unroll")                                                        \
        for (int rr = 0; rr < 2; rr++) {                                         \
            int r = lrow + rr * 128;                                             \
            int sw = (r >> 1) & 3;                                               \
            const __half* sh = Ah + (size_t)(mbaseA + r) * D_HID + kk;           \
            _Pragma("unroll")                                                    \
            for (int j = 0; j < 2; j++) {                                        \
                int blk = lb0 + j;                                               \
                uint32_t d = st0 + r * 64 + ((blk ^ sw) << 4);                   \
                asm volatile("cp.async.cg.shared.global [%0], [%1], 16;"         \
                             :: "r"(d), "l"(sh + blk * 8));                      \
            }                                                                    \
        }                                                                        \
        {                                                                        \
            int r = lrow;                                                        \
            int sw = (r >> 1) & 3;                                               \
            const __half* sh = Bh + (size_t)(nbaseB + r) * D_HID + kk;           \
            const __half* sl = Bl + (size_t)(nbaseB + r) * D_HID + kk;           \
            _Pragma("unroll")                                                    \
            for (int j = 0; j < 2; j++) {                                        \
                int blk = lb0 + j;                                               \
                uint32_t d = st0 + PLANE_A + r * 64 + ((blk ^ sw) << 4);         \
                asm volatile("cp.async.cg.shared.global [%0], [%1], 16;"         \
                             :: "r"(d), "l"(sh + blk * 8));                      \
                asm volatile("cp.async.cg.shared.global [%0], [%1], 16;"         \
                             :: "r"(d + PLANE_B), "l"(sl + blk * 8));            \
            }                                                                    \
        }                                                                        \
    } while (0)

    #pragma unroll
    for (int s = 0; s < NSTAGE - 1; s++) {
        LOAD_CHUNK(s, s);
        asm volatile("cp.async.commit_group;");
    }

    for (int i = 0; i < NCHUNK; i++) {
        asm volatile("cp.async.wait_group %0;" :: "n"(NSTAGE - 2));
        __syncthreads();

        if (i + NSTAGE - 1 < NCHUNK)
            LOAD_CHUNK(i + NSTAGE - 1, (i + NSTAGE - 1) & (NSTAGE - 1));
        asm volatile("cp.async.commit_group;");

        uint32_t st = sb + (i & (NSTAGE - 1)) * STAGE_BYTES;
        #pragma unroll
        for (int s = 0; s < 2; s++) {
            uint32_t bh[16], bl[16];
            #pragma unroll
            for (int pk = 0; pk < 4; pk++) {
                uint32_t ad = st + PLANE_A + bOff[pk]
                            + (((2 * s + bKb) ^ bSw[pk]) << 4);
                LDSM4(bh[pk*4+0], bh[pk*4+1], bh[pk*4+2], bh[pk*4+3], ad);
                LDSM4(bl[pk*4+0], bl[pk*4+1], bl[pk*4+2], bl[pk*4+3], ad + PLANE_B);
            }
            uint32_t ah[4][4];
            #pragma unroll
            for (int mt = 0; mt < 4; mt++) {
                uint32_t ad = st + aOff[mt] + (((2 * s + aKb) ^ aSw[mt]) << 4);
                LDSM4(ah[mt][0], ah[mt][1], ah[mt][2], ah[mt][3], ad);
            }
            #pragma unroll
            for (int mt = 0; mt < 4; mt++)
                #pragma unroll
                for (int nt = 0; nt < 8; nt++)
                    MMA_F16(acc[mt][nt], ah[mt], bh[nt*2], bh[nt*2+1]);
            #pragma unroll
            for (int mt = 0; mt < 4; mt++)
                #pragma unroll
                for (int nt = 0; nt < 8; nt++)
                    MMA_F16(acc[mt][nt], ah[mt], bl[nt*2], bl[nt*2+1]);
        }
    }

    #pragma unroll
    for (int mt = 0; mt < 4; mt++) {
        int row0 = blockIdx.y * 256 + wm + mt * 16 + (lane >> 2);
        #pragma unroll
        for (int nt = 0; nt < 8; nt++) {
            int col = blockIdx.x * 128 + wn + nt * 8 + (lane & 3) * 2;
            float b0 = bias[col], b1 = bias[col + 1];
            float2 v0, v1;
            v0.x = acc[mt][nt][0] + b0; v0.y = acc[mt][nt][1] + b1;
            v1.x = acc[mt][nt][2] + b0; v1.y = acc[mt][nt][3] + b1;
            *(float2*)(C + (size_t)row0 * ldc + col) = v0;
            *(float2*)(C + (size_t)(row0 + 8) * ldc + col) = v1;
        }
    }
}

// ---------------------------------------------------------------------------
// Vectorized fused attention (R9) — xs now written as single fp16 plane.
// ---------------------------------------------------------------------------
#define SROW 68

__global__ __launch_bounds__(256) void attn_fused_kernel(float* __restrict__ attn_out,
                                                         int write_attn)
{
    __shared__ float sq[16 * SROW];
    __shared__ float sk[16 * SROW];
    __shared__ float sv[16 * SROW];
    __shared__ float sc[16][17];

    int token = blockIdx.x;
    int tid   = threadIdx.x;
    int s     = token & (SEQ - 1);
    int b     = token >> 11;

    const float4* qrow = (const float4*)(g_q  + (size_t)token * D_HID);
    const float4* krow = (const float4*)(g_kv + (size_t)token * (2 * D_HID));
    const float4* vrow = krow + (D_HID / 4);

    {
        int i0 = tid * 4;
        int j0 = i0 & 511;
        const float4* cs = (const float4*)(g_cos + (s << 9) + j0);
        const float4* sn = (const float4*)(g_sin + (s << 9) + j0);
        float4 c4 = cs[0], s4 = sn[0];
        float4 qv = qrow[tid], qp = qrow[tid ^ 128];
        float4 kv = krow[tid], kp = krow[tid ^ 128];
        float sgn = (i0 < 512) ? -1.0f : 1.0f;
        float4 rq, rk;
        rq.x = qv.x * c4.x + sgn * qp.x * s4.x;
        rq.y = qv.y * c4.y + sgn * qp.y * s4.y;
        rq.z = qv.z * c4.z + sgn * qp.z * s4.z;
        rq.w = qv.w * c4.w + sgn * qp.w * s4.w;
        rk.x = kv.x * c4.x + sgn * kp.x * s4.x;
        rk.y = kv.y * c4.y + sgn * kp.y * s4.y;
        rk.z = kv.z * c4.z + sgn * kp.z * s4.z;
        rk.w = kv.w * c4.w + sgn * kp.w * s4.w;
        int row = tid >> 4;
        int c4i = tid & 15;
        *(float4*)(sq + row * SROW + c4i * 4) = rq;
        *(float4*)(sk + row * SROW + c4i * 4) = rk;
        *(float4*)(sv + row * SROW + c4i * 4) = vrow[tid];
    }
    __syncthreads();

    int h = tid >> 4, t = tid & 15;
    {
        const float4* q4 = (const float4*)(sq + h * SROW);
        const float4* k4 = (const float4*)(sk + t * SROW);
        float ax = 0.0f, ay = 0.0f, az = 0.0f, aw = 0.0f;
        #pragma unroll
        for (int dd = 0; dd < 16; dd++) {
            float4 a = q4[dd], bb = k4[dd];
            ax = fmaf(a.x, bb.x, ax);
            ay = fmaf(a.y, bb.y, ay);
            az = fmaf(a.z, bb.z, az);
            aw = fmaf(a.w, bb.w, aw);
        }
        float sco = (ax + ay + az + aw) * 0.125f;

        float m = sco;
        #pragma unroll
        for (int o = 8; o; o >>= 1)
            m = fmaxf(m, __shfl_xor_sync(0xffffffffu, m, o));
        float e = expf(sco - m);
        float sum = e;
        #pragma unroll
        for (int o = 8; o; o >>= 1)
            sum += __shfl_xor_sync(0xffffffffu, sum, o);
        float p = e / sum;
        sc[h][t] = p;
        if (write_attn)
            attn_out[(size_t)token * 256 + tid] = p;
    }
    __syncthreads();

    {
        int d4 = tid & 15;
        const float4* v4 = (const float4*)(sv) + d4;
        float4 acc = make_float4(0.0f, 0.0f, 0.0f, 0.0f);
        #pragma unroll
        for (int tt = 0; tt < 16; tt++) {
            float p = sc[h][tt];
            float4 vv = v4[tt * (SROW / 4)];
            acc.x = fmaf(p, vv.x, acc.x);
            acc.y = fmaf(p, vv.y, acc.y);
            acc.z = fmaf(p, vv.z, acc.z);
            acc.w = fmaf(p, vv.w, acc.w);
        }
        size_t xbase = ((size_t)b * SEQ + (h * 128 + (s >> 4))) * D_HID
                     + ((s & 15) << 6) + d4 * 4;
        __half2 p0 = __floats2half2_rn(acc.x, acc.y);
        __half2 p1 = __floats2half2_rn(acc.z, acc.w);
        uint2 u;
        u.x = *(uint32_t*)&p0;
        u.y = *(uint32_t*)&p1;
        *(uint2*)(g_xs_h + xbase) = u;
    }
}

// ---------------------------------------------------------------------------
extern "C" void kernel_launch(void* const* d_in, const int* in_sizes, int n_in,
                              void* d_out, int out_size)
{
    const float* inputs  = (const float*)d_in[0];
    const float* context = (const float*)d_in[1];
    const float* Wq = (const float*)d_in[2];
    const float* bq = (const float*)d_in[3];
    const float* Wk = (const float*)d_in[4];
    const float* bk = (const float*)d_in[5];
    const float* Wv = (const float*)d_in[6];
    const float* bv = (const float*)d_in[7];
    const float* Wo = (const float*)d_in[8];
    const float* bo = (const float*)d_in[9];
    float* out = (float*)d_out;

    float *q, *kv, *bkv;
    __half *inh, *cxh, *xsh, *wth, *wtl;
    cudaGetSymbolAddress((void**)&q,   g_q);
    cudaGetSymbolAddress((void**)&kv,  g_kv);
    cudaGetSymbolAddress((void**)&bkv, g_bkv);
    cudaGetSymbolAddress((void**)&inh, g_in_h);
    cudaGetSymbolAddress((void**)&cxh, g_cx_h);
    cudaGetSymbolAddress((void**)&xsh, g_xs_h);
    cudaGetSymbolAddress((void**)&wth, g_wt_h);
    cudaGetSymbolAddress((void**)&wtl, g_wt_l);

    cudaFuncSetAttribute(gemm_f16_2t,
                         cudaFuncAttributeMaxDynamicSharedMemorySize, GEMM_SMEM);

    const size_t WSZ = (size_t)D_HID * D_HID;

    // 1) fused prep
    prep_kernel<<<16392, 256>>>(inputs, context, Wq, Wk, Wv, Wo, bk, bv);

    // 2) Q projection (N=1024)
    {
        dim3 g(8, 16);
        gemm_f16_2t<<<g, 256, GEMM_SMEM>>>(inh, wth + 0*WSZ, wtl + 0*WSZ,
                                           bq, q, D_HID);
    }
    // 3) K+V merged projection (N=2048)
    {
        dim3 g(16, 16);
        gemm_f16_2t<<<g, 256, GEMM_SMEM>>>(cxh, wth + 1*WSZ, wtl + 1*WSZ,
                                           bkv, kv, 2 * D_HID);
    }

    // 4) fused vectorized RoPE + head-attention + scrambled fp16 ctx
    int write_attn = (out_size >= OUT_MAIN + ATTN_ELEMS) ? 1 : 0;
    attn_fused_kernel<<<MROWS, 256>>>(out + OUT_MAIN, write_attn);

    // 5) final projection
    {
        dim3 g(8, 16);
        gemm_f16_2t<<<g, 256, GEMM_SMEM>>>(xsh, wth + 3*WSZ, wtl + 3*WSZ,
                                           bo, out, D_HID);
    }
}

// round 11
// speedup vs baseline: 5.1473x; 1.4322x over previous
#include <cuda_runtime.h>
#include <cuda_fp16.h>
#include <math.h>
#include <stdint.h>

// Shapes (fixed)
#define D_HID 1024
#define SEQ   2048
#define BATCH 2
#define HEADS 16
#define HD    64
#define MROWS (BATCH*SEQ)                 // 4096
#define OUT_MAIN (MROWS*D_HID)            // 4194304
#define ATTN_ELEMS (MROWS*HEADS*HEADS)    // 1048576

// fp32 scratch
__device__ float g_q [MROWS*D_HID];
__device__ float g_kv[MROWS*2*D_HID];     // packed rows: k | v
__device__ float g_bkv[2*D_HID];          // bk || bv
__device__ float g_cos[SEQ*(D_HID/2)];
__device__ float g_sin[SEQ*(D_HID/2)];

// fp16 operand planes (single plane each)
__device__ __half g_in_h[MROWS*D_HID];
__device__ __half g_cx_h[MROWS*D_HID];
__device__ __half g_xs_h[MROWS*D_HID];
__device__ __half g_wt_h[4*D_HID*D_HID];  // W^T (Wq,Wk,Wv,Wo)

__device__ __forceinline__ uint32_t smem_u32(const void* p) {
    uint32_t a;
    asm("{ .reg .u64 t; cvta.to.shared.u64 t, %1; cvt.u32.u64 %0, t; }"
        : "=r"(a) : "l"(p));
    return a;
}

// ---------------------------------------------------------------------------
// Fused prep kernel:
//   [0,8192)      : fp32 -> fp16 convert of inputs / context
//   [8192,12288)  : W transpose + fp16 convert for 4 weights
//   [12288,16384) : RoPE tables
//   [16384,16392) : pack bk||bv
// ---------------------------------------------------------------------------
__global__ __launch_bounds__(256)
void prep_kernel(const float* __restrict__ inputs, const float* __restrict__ context,
                 const float* __restrict__ W0, const float* __restrict__ W1,
                 const float* __restrict__ W2, const float* __restrict__ W3,
                 const float* __restrict__ bk, const float* __restrict__ bv)
{
    int blk = blockIdx.x;
    int tid = threadIdx.x;

    if (blk < 8192) {
        int which = blk >> 12;
        int idx = ((blk & 4095) << 8) | tid;        // float4 index
        const float4* src = (const float4*)(which ? context : inputs);
        uint2* h = (uint2*)(which ? g_cx_h : g_in_h);
        float4 v = src[idx];
        __half2 p0 = __floats2half2_rn(v.x, v.y);
        __half2 p1 = __floats2half2_rn(v.z, v.w);
        uint2 u;
        u.x = *(uint32_t*)&p0;
        u.y = *(uint32_t*)&p1;
        h[idx] = u;
    } else if (blk < 12288) {
        __shared__ float t[32][33];
        int r  = blk - 8192;
        int z  = r >> 10;
        int bi = r & 1023;
        int x0 = (bi & 31) * 32;
        int y0 = (bi >> 5) * 32;
        const float* W = (z == 0) ? W0 : (z == 1) ? W1 : (z == 2) ? W2 : W3;
        __half* h = g_wt_h + (size_t)z * D_HID * D_HID;
        int tx = tid & 31, ty = tid >> 5;
        #pragma unroll
        for (int j = 0; j < 4; j++)
            t[ty + 8 * j][tx] = W[(size_t)(y0 + ty + 8 * j) * D_HID + x0 + tx];
        __syncthreads();
        #pragma unroll
        for (int j = 0; j < 4; j++) {
            int rr = ty + 8 * j;
            h[(size_t)(x0 + rr) * D_HID + y0 + tx] = __float2half_rn(t[tx][rr]);
        }
    } else if (blk < 16384) {
        int idx = ((blk - 12288) << 8) | tid;
        int s = idx >> 9;
        int j = idx & 511;
        float inv = expf(-(float)j * (9.210340371976184f / 512.0f));
        float arg = (float)s * inv;
        float sv, cv;
        sincosf(arg, &sv, &cv);
        g_cos[idx] = cv;
        g_sin[idx] = sv;
    } else {
        int i = ((blk - 16384) << 8) | tid;
        g_bkv[i] = (i < D_HID) ? bk[i] : bv[i - D_HID];
    }
}

// ---------------------------------------------------------------------------
// fp16 GEMM: C[M,N] = A_f16 @ W_f16 + bias   (fp32 accum)
//   CTA 256x128, 8 warps of 64x64, K-chunk 32, 4-stage cp.async.
// ---------------------------------------------------------------------------
#define KC 32
#define NSTAGE 4
#define PLANE_A 16384                    // 256 rows * 64B
#define PLANE_B 8192                     // 128 rows * 64B
#define STAGE_BYTES (PLANE_A + PLANE_B)      // 24576
#define GEMM_SMEM (NSTAGE*STAGE_BYTES)       // 98304
#define NCHUNK (D_HID/KC)                // 32

#define LDSM4(r0,r1,r2,r3,addr) \
    asm volatile("ldmatrix.sync.aligned.m8n8.x4.shared.b16 {%0,%1,%2,%3}, [%4];" \
        : "=r"(r0), "=r"(r1), "=r"(r2), "=r"(r3) : "r"(addr))

#define MMA_F16(d, a, b0v, b1v) \
    asm volatile("mma.sync.aligned.m16n8k16.row.col.f32.f16.f16.f32 " \
        "{%0,%1,%2,%3}, {%4,%5,%6,%7}, {%8,%9}, {%0,%1,%2,%3};" \
        : "+f"((d)[0]), "+f"((d)[1]), "+f"((d)[2]), "+f"((d)[3]) \
        : "r"((a)[0]), "r"((a)[1]), "r"((a)[2]), "r"((a)[3]), "r"(b0v), "r"(b1v))

__global__ __launch_bounds__(256, 1)
void gemm_f16(const __half* __restrict__ Ah,
              const __half* __restrict__ Bh,
              const float* __restrict__ bias, float* __restrict__ C,
              int ldc)
{
    extern __shared__ char smem[];
    uint32_t sb = smem_u32(smem);
    int tid = threadIdx.x, lane = tid & 31, wid = tid >> 5;
    int wm = (wid & 3) * 64;
    int wn = (wid >> 2) * 64;

    int mbaseA = blockIdx.y * 256;
    int nbaseB = blockIdx.x * 128;

    int lrow = tid >> 1;
    int lb0  = (tid & 1) * 2;

    uint32_t aOff[4]; int aSw[4];
    #pragma unroll
    for (int mt = 0; mt < 4; mt++) {
        int r = wm + mt * 16 + (lane & 7) + ((lane >> 3) & 1) * 8;
        aOff[mt] = r * 64;
        aSw[mt] = (r >> 1) & 3;
    }
    int g = lane >> 3;
    uint32_t bOff[4]; int bSw[4];
    #pragma unroll
    for (int pk = 0; pk < 4; pk++) {
        int r = wn + pk * 16 + ((g >> 1) << 3) + (lane & 7);
        bOff[pk] = r * 64;
        bSw[pk] = (r >> 1) & 3;
    }
    int aKb = lane >> 4;
    int bKb = g & 1;

    float acc[4][8][4];
    #pragma unroll
    for (int i = 0; i < 4; i++)
        #pragma unroll
        for (int j = 0; j < 8; j++)
            #pragma unroll
            for (int c = 0; c < 4; c++) acc[i][j][c] = 0.0f;

    #define LOAD_CHUNK(chunk, stage) do {                                        \
        uint32_t st0 = sb + (stage) * STAGE_BYTES;                               \
        int kk = (chunk) * KC;                                                   \
        _Pragma("unroll")                                                        \
        for (int rr = 0; rr < 2; rr++) {                                         \
            int r = lrow + rr * 128;                                             \
            int sw = (r >> 1) & 3;                                               \
            const __half* sh = Ah + (size_t)(mbaseA + r) * D_HID + kk;           \
            _Pragma("unroll")                                                    \
            for (int j = 0; j < 2; j++) {                                        \
                int blk = lb0 + j;                                               \
                uint32_t d = st0 + r * 64 + ((blk ^ sw) << 4);                   \
                asm volatile("cp.async.cg.shared.global [%0], [%1], 16;"         \
                             :: "r"(d), "l"(sh + blk * 8));                      \
            }                                                                    \
        }                                                                        \
        {                                                                        \
            int r = lrow;                                                        \
            int sw = (r >> 1) & 3;                                               \
            const __half* sh = Bh + (size_t)(nbaseB + r) * D_HID + kk;           \
            _Pragma("unroll")                                                    \
            for (int j = 0; j < 2; j++) {                                        \
                int blk = lb0 + j;                                               \
                uint32_t d = st0 + PLANE_A + r * 64 + ((blk ^ sw) << 4);         \
                asm volatile("cp.async.cg.shared.global [%0], [%1], 16;"         \
                             :: "r"(d), "l"(sh + blk * 8));                      \
            }                                                                    \
        }                                                                        \
    } while (0)

    #pragma unroll
    for (int s = 0; s < NSTAGE - 1; s++) {
        LOAD_CHUNK(s, s);
        asm volatile("cp.async.commit_group;");
    }

    for (int i = 0; i < NCHUNK; i++) {
        asm volatile("cp.async.wait_group %0;" :: "n"(NSTAGE - 2));
        __syncthreads();

        if (i + NSTAGE - 1 < NCHUNK)
            LOAD_CHUNK(i + NSTAGE - 1, (i + NSTAGE - 1) & (NSTAGE - 1));
        asm volatile("cp.async.commit_group;");

        uint32_t st = sb + (i & (NSTAGE - 1)) * STAGE_BYTES;
        #pragma unroll
        for (int s = 0; s < 2; s++) {
            uint32_t bh[16];
            #pragma unroll
            for (int pk = 0; pk < 4; pk++) {
                uint32_t ad = st + PLANE_A + bOff[pk]
                            + (((2 * s + bKb) ^ bSw[pk]) << 4);
                LDSM4(bh[pk*4+0], bh[pk*4+1], bh[pk*4+2], bh[pk*4+3], ad);
            }
            uint32_t ah[4][4];
            #pragma unroll
            for (int mt = 0; mt < 4; mt++) {
                uint32_t ad = st + aOff[mt] + (((2 * s + aKb) ^ aSw[mt]) << 4);
                LDSM4(ah[mt][0], ah[mt][1], ah[mt][2], ah[mt][3], ad);
            }
            #pragma unroll
            for (int mt = 0; mt < 4; mt++)
                #pragma unroll
                for (int nt = 0; nt < 8; nt++)
                    MMA_F16(acc[mt][nt], ah[mt], bh[nt*2], bh[nt*2+1]);
        }
    }

    #pragma unroll
    for (int mt = 0; mt < 4; mt++) {
        int row0 = blockIdx.y * 256 + wm + mt * 16 + (lane >> 2);
        #pragma unroll
        for (int nt = 0; nt < 8; nt++) {
            int col = blockIdx.x * 128 + wn + nt * 8 + (lane & 3) * 2;
            float b0 = bias[col], b1 = bias[col + 1];
            float2 v0, v1;
            v0.x = acc[mt][nt][0] + b0; v0.y = acc[mt][nt][1] + b1;
            v1.x = acc[mt][nt][2] + b0; v1.y = acc[mt][nt][3] + b1;
            *(float2*)(C + (size_t)row0 * ldc + col) = v0;
            *(float2*)(C + (size_t)(row0 + 8) * ldc + col) = v1;
        }
    }
}

// ---------------------------------------------------------------------------
// Vectorized fused attention (R9/R10) — xs written as single fp16 plane.
// ---------------------------------------------------------------------------
#define SROW 68

__global__ __launch_bounds__(256) void attn_fused_kernel(float* __restrict__ attn_out,
                                                         int write_attn)
{
    __shared__ float sq[16 * SROW];
    __shared__ float sk[16 * SROW];
    __shared__ float sv[16 * SROW];
    __shared__ float sc[16][17];

    int token = blockIdx.x;
    int tid   = threadIdx.x;
    int s     = token & (SEQ - 1);
    int b     = token >> 11;

    const float4* qrow = (const float4*)(g_q  + (size_t)token * D_HID);
    const float4* krow = (const float4*)(g_kv + (size_t)token * (2 * D_HID));
    const float4* vrow = krow + (D_HID / 4);

    {
        int i0 = tid * 4;
        int j0 = i0 & 511;
        const float4* cs = (const float4*)(g_cos + (s << 9) + j0);
        const float4* sn = (const float4*)(g_sin + (s << 9) + j0);
        float4 c4 = cs[0], s4 = sn[0];
        float4 qv = qrow[tid], qp = qrow[tid ^ 128];
        float4 kv = krow[tid], kp = krow[tid ^ 128];
        float sgn = (i0 < 512) ? -1.0f : 1.0f;
        float4 rq, rk;
        rq.x = qv.x * c4.x + sgn * qp.x * s4.x;
        rq.y = qv.y * c4.y + sgn * qp.y * s4.y;
        rq.z = qv.z * c4.z + sgn * qp.z * s4.z;
        rq.w = qv.w * c4.w + sgn * qp.w * s4.w;
        rk.x = kv.x * c4.x + sgn * kp.x * s4.x;
        rk.y = kv.y * c4.y + sgn * kp.y * s4.y;
        rk.z = kv.z * c4.z + sgn * kp.z * s4.z;
        rk.w = kv.w * c4.w + sgn * kp.w * s4.w;
        int row = tid >> 4;
        int c4i = tid & 15;
        *(float4*)(sq + row * SROW + c4i * 4) = rq;
        *(float4*)(sk + row * SROW + c4i * 4) = rk;
        *(float4*)(sv + row * SROW + c4i * 4) = vrow[tid];
    }
    __syncthreads();

    int h = tid >> 4, t = tid & 15;
    {
        const float4* q4 = (const float4*)(sq + h * SROW);
        const float4* k4 = (const float4*)(sk + t * SROW);
        float ax = 0.0f, ay = 0.0f, az = 0.0f, aw = 0.0f;
        #pragma unroll
        for (int dd = 0; dd < 16; dd++) {
            float4 a = q4[dd], bb = k4[dd];
            ax = fmaf(a.x, bb.x, ax);
            ay = fmaf(a.y, bb.y, ay);
            az = fmaf(a.z, bb.z, az);
            aw = fmaf(a.w, bb.w, aw);
        }
        float sco = (ax + ay + az + aw) * 0.125f;

        float m = sco;
        #pragma unroll
        for (int o = 8; o; o >>= 1)
            m = fmaxf(m, __shfl_xor_sync(0xffffffffu, m, o));
        float e = expf(sco - m);
        float sum = e;
        #pragma unroll
        for (int o = 8; o; o >>= 1)
            sum += __shfl_xor_sync(0xffffffffu, sum, o);
        float p = e / sum;
        sc[h][t] = p;
        if (write_attn)
            attn_out[(size_t)token * 256 + tid] = p;
    }
    __syncthreads();

    {
        int d4 = tid & 15;
        const float4* v4 = (const float4*)(sv) + d4;
        float4 acc = make_float4(0.0f, 0.0f, 0.0f, 0.0f);
        #pragma unroll
        for (int tt = 0; tt < 16; tt++) {
            float p = sc[h][tt];
            float4 vv = v4[tt * (SROW / 4)];
            acc.x = fmaf(p, vv.x, acc.x);
            acc.y = fmaf(p, vv.y, acc.y);
            acc.z = fmaf(p, vv.z, acc.z);
            acc.w = fmaf(p, vv.w, acc.w);
        }
        size_t xbase = ((size_t)b * SEQ + (h * 128 + (s >> 4))) * D_HID
                     + ((s & 15) << 6) + d4 * 4;
        __half2 p0 = __floats2half2_rn(acc.x, acc.y);
        __half2 p1 = __floats2half2_rn(acc.z, acc.w);
        uint2 u;
        u.x = *(uint32_t*)&p0;
        u.y = *(uint32_t*)&p1;
        *(uint2*)(g_xs_h + xbase) = u;
    }
}

// ---------------------------------------------------------------------------
extern "C" void kernel_launch(void* const* d_in, const int* in_sizes, int n_in,
                              void* d_out, int out_size)
{
    const float* inputs  = (const float*)d_in[0];
    const float* context = (const float*)d_in[1];
    const float* Wq = (const float*)d_in[2];
    const float* bq = (const float*)d_in[3];
    const float* Wk = (const float*)d_in[4];
    const float* bk = (const float*)d_in[5];
    const float* Wv = (const float*)d_in[6];
    const float* bv = (const float*)d_in[7];
    const float* Wo = (const float*)d_in[8];
    const float* bo = (const float*)d_in[9];
    float* out = (float*)d_out;

    float *q, *kv, *bkv;
    __half *inh, *cxh, *xsh, *wth;
    cudaGetSymbolAddress((void**)&q,   g_q);
    cudaGetSymbolAddress((void**)&kv,  g_kv);
    cudaGetSymbolAddress((void**)&bkv, g_bkv);
    cudaGetSymbolAddress((void**)&inh, g_in_h);
    cudaGetSymbolAddress((void**)&cxh, g_cx_h);
    cudaGetSymbolAddress((void**)&xsh, g_xs_h);
    cudaGetSymbolAddress((void**)&wth, g_wt_h);

    cudaFuncSetAttribute(gemm_f16,
                         cudaFuncAttributeMaxDynamicSharedMemorySize, GEMM_SMEM);

    const size_t WSZ = (size_t)D_HID * D_HID;

    // 1) fused prep
    prep_kernel<<<16392, 256>>>(inputs, context, Wq, Wk, Wv, Wo, bk, bv);

    // 2) Q projection (N=1024)
    {
        dim3 g(8, 16);
        gemm_f16<<<g, 256, GEMM_SMEM>>>(inh, wth + 0*WSZ, bq, q, D_HID);
    }
    // 3) K+V merged projection (N=2048)
    {
        dim3 g(16, 16);
        gemm_f16<<<g, 256, GEMM_SMEM>>>(cxh, wth + 1*WSZ, bkv, kv, 2 * D_HID);
    }

    // 4) fused vectorized RoPE + head-attention + scrambled fp16 ctx
    int write_attn = (out_size >= OUT_MAIN + ATTN_ELEMS) ? 1 : 0;
    attn_fused_kernel<<<MROWS, 256>>>(out + OUT_MAIN, write_attn);

    // 5) final projection
    {
        dim3 g(8, 16);
        gemm_f16<<<g, 256, GEMM_SMEM>>>(xsh, wth + 3*WSZ, bo, out, D_HID);
    }
}

// round 12
// speedup vs baseline: 5.1923x; 1.0087x over previous
#include <cuda_runtime.h>
#include <cuda_fp16.h>
#include <math.h>
#include <stdint.h>

// Shapes (fixed)
#define D_HID 1024
#define SEQ   2048
#define BATCH 2
#define HEADS 16
#define HD    64
#define MROWS (BATCH*SEQ)                 // 4096
#define OUT_MAIN (MROWS*D_HID)            // 4194304
#define ATTN_ELEMS (MROWS*HEADS*HEADS)    // 1048576

// fp16 q/kv planes (GEMM outputs)
__device__ __half g_q16 [MROWS*D_HID];
__device__ __half g_kv16[MROWS*2*D_HID];  // packed rows: k | v
__device__ float  g_bkv[2*D_HID];         // bk || bv
__device__ float  g_cos[SEQ*(D_HID/2)];
__device__ float  g_sin[SEQ*(D_HID/2)];

// fp16 operand planes
__device__ __half g_in_h[MROWS*D_HID];
__device__ __half g_cx_h[MROWS*D_HID];
__device__ __half g_xs_h[MROWS*D_HID];
__device__ __half g_wt_h[4*D_HID*D_HID];  // W^T (Wq,Wk,Wv,Wo)

__device__ __forceinline__ uint32_t smem_u32(const void* p) {
    uint32_t a;
    asm("{ .reg .u64 t; cvta.to.shared.u64 t, %1; cvt.u32.u64 %0, t; }"
        : "=r"(a) : "l"(p));
    return a;
}

// ---------------------------------------------------------------------------
// Fused prep kernel (unchanged from R11)
// ---------------------------------------------------------------------------
__global__ __launch_bounds__(256)
void prep_kernel(const float* __restrict__ inputs, const float* __restrict__ context,
                 const float* __restrict__ W0, const float* __restrict__ W1,
                 const float* __restrict__ W2, const float* __restrict__ W3,
                 const float* __restrict__ bk, const float* __restrict__ bv)
{
    int blk = blockIdx.x;
    int tid = threadIdx.x;

    if (blk < 8192) {
        int which = blk >> 12;
        int idx = ((blk & 4095) << 8) | tid;        // float4 index
        const float4* src = (const float4*)(which ? context : inputs);
        uint2* h = (uint2*)(which ? g_cx_h : g_in_h);
        float4 v = src[idx];
        __half2 p0 = __floats2half2_rn(v.x, v.y);
        __half2 p1 = __floats2half2_rn(v.z, v.w);
        uint2 u;
        u.x = *(uint32_t*)&p0;
        u.y = *(uint32_t*)&p1;
        h[idx] = u;
    } else if (blk < 12288) {
        __shared__ float t[32][33];
        int r  = blk - 8192;
        int z  = r >> 10;
        int bi = r & 1023;
        int x0 = (bi & 31) * 32;
        int y0 = (bi >> 5) * 32;
        const float* W = (z == 0) ? W0 : (z == 1) ? W1 : (z == 2) ? W2 : W3;
        __half* h = g_wt_h + (size_t)z * D_HID * D_HID;
        int tx = tid & 31, ty = tid >> 5;
        #pragma unroll
        for (int j = 0; j < 4; j++)
            t[ty + 8 * j][tx] = W[(size_t)(y0 + ty + 8 * j) * D_HID + x0 + tx];
        __syncthreads();
        #pragma unroll
        for (int j = 0; j < 4; j++) {
            int rr = ty + 8 * j;
            h[(size_t)(x0 + rr) * D_HID + y0 + tx] = __float2half_rn(t[tx][rr]);
        }
    } else if (blk < 16384) {
        int idx = ((blk - 12288) << 8) | tid;
        int s = idx >> 9;
        int j = idx & 511;
        float inv = expf(-(float)j * (9.210340371976184f / 512.0f));
        float arg = (float)s * inv;
        float sv, cv;
        sincosf(arg, &sv, &cv);
        g_cos[idx] = cv;
        g_sin[idx] = sv;
    } else {
        int i = ((blk - 16384) << 8) | tid;
        g_bkv[i] = (i < D_HID) ? bk[i] : bv[i - D_HID];
    }
}

// ---------------------------------------------------------------------------
// fp16 GEMM: C[M,N] = A_f16 @ W_f16 + bias (fp32 accum)
//   OUT_HALF=1 writes __half C; OUT_HALF=0 writes float C.
//   CTA 256x128, 8 warps of 64x64, K-chunk 32, 4-stage cp.async.
// ---------------------------------------------------------------------------
#define KC 32
#define NSTAGE 4
#define PLANE_A 16384                    // 256 rows * 64B
#define PLANE_B 8192                     // 128 rows * 64B
#define STAGE_BYTES (PLANE_A + PLANE_B)      // 24576
#define GEMM_SMEM (NSTAGE*STAGE_BYTES)       // 98304
#define NCHUNK (D_HID/KC)                // 32

#define LDSM4(r0,r1,r2,r3,addr) \
    asm volatile("ldmatrix.sync.aligned.m8n8.x4.shared.b16 {%0,%1,%2,%3}, [%4];" \
        : "=r"(r0), "=r"(r1), "=r"(r2), "=r"(r3) : "r"(addr))

#define MMA_F16(d, a, b0v, b1v) \
    asm volatile("mma.sync.aligned.m16n8k16.row.col.f32.f16.f16.f32 " \
        "{%0,%1,%2,%3}, {%4,%5,%6,%7}, {%8,%9}, {%0,%1,%2,%3};" \
        : "+f"((d)[0]), "+f"((d)[1]), "+f"((d)[2]), "+f"((d)[3]) \
        : "r"((a)[0]), "r"((a)[1]), "r"((a)[2]), "r"((a)[3]), "r"(b0v), "r"(b1v))

template<int OUT_HALF>
__global__ __launch_bounds__(256, 1)
void gemm_f16(const __half* __restrict__ Ah,
              const __half* __restrict__ Bh,
              const float* __restrict__ bias, void* __restrict__ Cv,
              int ldc)
{
    extern __shared__ char smem[];
    uint32_t sb = smem_u32(smem);
    int tid = threadIdx.x, lane = tid & 31, wid = tid >> 5;
    int wm = (wid & 3) * 64;
    int wn = (wid >> 2) * 64;

    int mbaseA = blockIdx.y * 256;
    int nbaseB = blockIdx.x * 128;

    int lrow = tid >> 1;
    int lb0  = (tid & 1) * 2;

    uint32_t aOff[4]; int aSw[4];
    #pragma unroll
    for (int mt = 0; mt < 4; mt++) {
        int r = wm + mt * 16 + (lane & 7) + ((lane >> 3) & 1) * 8;
        aOff[mt] = r * 64;
        aSw[mt] = (r >> 1) & 3;
    }
    int g = lane >> 3;
    uint32_t bOff[4]; int bSw[4];
    #pragma unroll
    for (int pk = 0; pk < 4; pk++) {
        int r = wn + pk * 16 + ((g >> 1) << 3) + (lane & 7);
        bOff[pk] = r * 64;
        bSw[pk] = (r >> 1) & 3;
    }
    int aKb = lane >> 4;
    int bKb = g & 1;

    float acc[4][8][4];
    #pragma unroll
    for (int i = 0; i < 4; i++)
        #pragma unroll
        for (int j = 0; j < 8; j++)
            #pragma unroll
            for (int c = 0; c < 4; c++) acc[i][j][c] = 0.0f;

    #define LOAD_CHUNK(chunk, stage) do {                                        \
        uint32_t st0 = sb + (stage) * STAGE_BYTES;                               \
        int kk = (chunk) * KC;                                                   \
        _Pragma("unroll")                                                        \
        for (int rr = 0; rr < 2; rr++) {                                         \
            int r = lrow + rr * 128;                                             \
            int sw = (r >> 1) & 3;                                               \
            const __half* sh = Ah + (size_t)(mbaseA + r) * D_HID + kk;           \
            _Pragma("unroll")                                                    \
            for (int j = 0; j < 2; j++) {                                        \
                int blk = lb0 + j;                                               \
                uint32_t d = st0 + r * 64 + ((blk ^ sw) << 4);                   \
                asm volatile("cp.async.cg.shared.global [%0], [%1], 16;"         \
                             :: "r"(d), "l"(sh + blk * 8));                      \
            }                                                                    \
        }                                                                        \
        {                                                                        \
            int r = lrow;                                                        \
            int sw = (r >> 1) & 3;                                               \
            const __half* sh = Bh + (size_t)(nbaseB + r) * D_HID + kk;           \
            _Pragma("unroll")                                                    \
            for (int j = 0; j < 2; j++) {                                        \
                int blk = lb0 + j;                                               \
                uint32_t d = st0 + PLANE_A + r * 64 + ((blk ^ sw) << 4);         \
                asm volatile("cp.async.cg.shared.global [%0], [%1], 16;"         \
                             :: "r"(d), "l"(sh + blk * 8));                      \
            }                                                                    \
        }                                                                        \
    } while (0)

    #pragma unroll
    for (int s = 0; s < NSTAGE - 1; s++) {
        LOAD_CHUNK(s, s);
        asm volatile("cp.async.commit_group;");
    }

    for (int i = 0; i < NCHUNK; i++) {
        asm volatile("cp.async.wait_group %0;" :: "n"(NSTAGE - 2));
        __syncthreads();

        if (i + NSTAGE - 1 < NCHUNK)
            LOAD_CHUNK(i + NSTAGE - 1, (i + NSTAGE - 1) & (NSTAGE - 1));
        asm volatile("cp.async.commit_group;");

        uint32_t st = sb + (i & (NSTAGE - 1)) * STAGE_BYTES;
        #pragma unroll
        for (int s = 0; s < 2; s++) {
            uint32_t bh[16];
            #pragma unroll
            for (int pk = 0; pk < 4; pk++) {
                uint32_t ad = st + PLANE_A + bOff[pk]
                            + (((2 * s + bKb) ^ bSw[pk]) << 4);
                LDSM4(bh[pk*4+0], bh[pk*4+1], bh[pk*4+2], bh[pk*4+3], ad);
            }
            uint32_t ah[4][4];
            #pragma unroll
            for (int mt = 0; mt < 4; mt++) {
                uint32_t ad = st + aOff[mt] + (((2 * s + aKb) ^ aSw[mt]) << 4);
                LDSM4(ah[mt][0], ah[mt][1], ah[mt][2], ah[mt][3], ad);
            }
            #pragma unroll
            for (int mt = 0; mt < 4; mt++)
                #pragma unroll
                for (int nt = 0; nt < 8; nt++)
                    MMA_F16(acc[mt][nt], ah[mt], bh[nt*2], bh[nt*2+1]);
        }
    }

    #pragma unroll
    for (int mt = 0; mt < 4; mt++) {
        int row0 = blockIdx.y * 256 + wm + mt * 16 + (lane >> 2);
        #pragma unroll
        for (int nt = 0; nt < 8; nt++) {
            int col = blockIdx.x * 128 + wn + nt * 8 + (lane & 3) * 2;
            float b0 = bias[col], b1 = bias[col + 1];
            float o00 = acc[mt][nt][0] + b0, o01 = acc[mt][nt][1] + b1;
            float o10 = acc[mt][nt][2] + b0, o11 = acc[mt][nt][3] + b1;
            if (OUT_HALF) {
                __half* C = (__half*)Cv;
                __half2 p0 = __floats2half2_rn(o00, o01);
                __half2 p1 = __floats2half2_rn(o10, o11);
                *(__half2*)(C + (size_t)row0 * ldc + col) = p0;
                *(__half2*)(C + (size_t)(row0 + 8) * ldc + col) = p1;
            } else {
                float* C = (float*)Cv;
                float2 v0; v0.x = o00; v0.y = o01;
                float2 v1; v1.x = o10; v1.y = o11;
                *(float2*)(C + (size_t)row0 * ldc + col) = v0;
                *(float2*)(C + (size_t)(row0 + 8) * ldc + col) = v1;
            }
        }
    }
}

// ---------------------------------------------------------------------------
// Vectorized fused attention — q/kv read as fp16, compute fp32.
// ---------------------------------------------------------------------------
#define SROW 68

__global__ __launch_bounds__(256) void attn_fused_kernel(float* __restrict__ attn_out,
                                                         int write_attn)
{
    __shared__ float sq[16 * SROW];
    __shared__ float sk[16 * SROW];
    __shared__ float sv[16 * SROW];
    __shared__ float sc[16][17];

    int token = blockIdx.x;
    int tid   = threadIdx.x;
    int s     = token & (SEQ - 1);
    int b     = token >> 11;

    const uint2* qrow = (const uint2*)(g_q16  + (size_t)token * D_HID);
    const uint2* krow = (const uint2*)(g_kv16 + (size_t)token * (2 * D_HID));
    const uint2* vrow = krow + (D_HID / 4);   // 1024 halves = 256 uint2

    // ---- load + RoPE (4 elems per thread per tensor) ----
    {
        int i0 = tid * 4;
        int j0 = i0 & 511;
        const float4* cs = (const float4*)(g_cos + (s << 9) + j0);
        const float4* sn = (const float4*)(g_sin + (s << 9) + j0);
        float4 c4 = cs[0], s4 = sn[0];

        uint2 uq  = qrow[tid],       uk  = krow[tid];
        uint2 uqp = qrow[tid ^ 128], ukp = krow[tid ^ 128];
        uint2 uv  = vrow[tid];
        float2 q01 = __half22float2(*(__half2*)&uq.x);
        float2 q23 = __half22float2(*(__half2*)&uq.y);
        float2 qp01 = __half22float2(*(__half2*)&uqp.x);
        float2 qp23 = __half22float2(*(__half2*)&uqp.y);
        float2 k01 = __half22float2(*(__half2*)&uk.x);
        float2 k23 = __half22float2(*(__half2*)&uk.y);
        float2 kp01 = __half22float2(*(__half2*)&ukp.x);
        float2 kp23 = __half22float2(*(__half2*)&ukp.y);
        float2 v01 = __half22float2(*(__half2*)&uv.x);
        float2 v23 = __half22float2(*(__half2*)&uv.y);

        float sgn = (i0 < 512) ? -1.0f : 1.0f;
        float4 rq, rk, vv;
        rq.x = q01.x * c4.x + sgn * qp01.x * s4.x;
        rq.y = q01.y * c4.y + sgn * qp01.y * s4.y;
        rq.z = q23.x * c4.z + sgn * qp23.x * s4.z;
        rq.w = q23.y * c4.w + sgn * qp23.y * s4.w;
        rk.x = k01.x * c4.x + sgn * kp01.x * s4.x;
        rk.y = k01.y * c4.y + sgn * kp01.y * s4.y;
        rk.z = k23.x * c4.z + sgn * kp23.x * s4.z;
        rk.w = k23.y * c4.w + sgn * kp23.y * s4.w;
        vv.x = v01.x; vv.y = v01.y; vv.z = v23.x; vv.w = v23.y;

        int row = tid >> 4;
        int c4i = tid & 15;
        *(float4*)(sq + row * SROW + c4i * 4) = rq;
        *(float4*)(sk + row * SROW + c4i * 4) = rk;
        *(float4*)(sv + row * SROW + c4i * 4) = vv;
    }
    __syncthreads();

    int h = tid >> 4, t = tid & 15;
    {
        const float4* q4 = (const float4*)(sq + h * SROW);
        const float4* k4 = (const float4*)(sk + t * SROW);
        float ax = 0.0f, ay = 0.0f, az = 0.0f, aw = 0.0f;
        #pragma unroll
        for (int dd = 0; dd < 16; dd++) {
            float4 a = q4[dd], bb = k4[dd];
            ax = fmaf(a.x, bb.x, ax);
            ay = fmaf(a.y, bb.y, ay);
            az = fmaf(a.z, bb.z, az);
            aw = fmaf(a.w, bb.w, aw);
        }
        float sco = (ax + ay + az + aw) * 0.125f;

        float m = sco;
        #pragma unroll
        for (int o = 8; o; o >>= 1)
            m = fmaxf(m, __shfl_xor_sync(0xffffffffu, m, o));
        float e = expf(sco - m);
        float sum = e;
        #pragma unroll
        for (int o = 8; o; o >>= 1)
            sum += __shfl_xor_sync(0xffffffffu, sum, o);
        float p = e / sum;
        sc[h][t] = p;
        if (write_attn)
            attn_out[(size_t)token * 256 + tid] = p;
    }
    __syncthreads();

    {
        int d4 = tid & 15;
        const float4* v4 = (const float4*)(sv) + d4;
        float4 acc = make_float4(0.0f, 0.0f, 0.0f, 0.0f);
        #pragma unroll
        for (int tt = 0; tt < 16; tt++) {
            float p = sc[h][tt];
            float4 vv = v4[tt * (SROW / 4)];
            acc.x = fmaf(p, vv.x, acc.x);
            acc.y = fmaf(p, vv.y, acc.y);
            acc.z = fmaf(p, vv.z, acc.z);
            acc.w = fmaf(p, vv.w, acc.w);
        }
        size_t xbase = ((size_t)b * SEQ + (h * 128 + (s >> 4))) * D_HID
                     + ((s & 15) << 6) + d4 * 4;
        __half2 p0 = __floats2half2_rn(acc.x, acc.y);
        __half2 p1 = __floats2half2_rn(acc.z, acc.w);
        uint2 u;
        u.x = *(uint32_t*)&p0;
        u.y = *(uint32_t*)&p1;
        *(uint2*)(g_xs_h + xbase) = u;
    }
}

// ---------------------------------------------------------------------------
extern "C" void kernel_launch(void* const* d_in, const int* in_sizes, int n_in,
                              void* d_out, int out_size)
{
    const float* inputs  = (const float*)d_in[0];
    const float* context = (const float*)d_in[1];
    const float* Wq = (const float*)d_in[2];
    const float* bq = (const float*)d_in[3];
    const float* Wk = (const float*)d_in[4];
    const float* bk = (const float*)d_in[5];
    const float* Wv = (const float*)d_in[6];
    const float* bv = (const float*)d_in[7];
    const float* Wo = (const float*)d_in[8];
    const float* bo = (const float*)d_in[9];
    float* out = (float*)d_out;

    float *bkv;
    __half *q16, *kv16, *inh, *cxh, *xsh, *wth;
    cudaGetSymbolAddress((void**)&q16,  g_q16);
    cudaGetSymbolAddress((void**)&kv16, g_kv16);
    cudaGetSymbolAddress((void**)&bkv,  g_bkv);
    cudaGetSymbolAddress((void**)&inh,  g_in_h);
    cudaGetSymbolAddress((void**)&cxh,  g_cx_h);
    cudaGetSymbolAddress((void**)&xsh,  g_xs_h);
    cudaGetSymbolAddress((void**)&wth,  g_wt_h);

    cudaFuncSetAttribute(gemm_f16<1>,
                         cudaFuncAttributeMaxDynamicSharedMemorySize, GEMM_SMEM);
    cudaFuncSetAttribute(gemm_f16<0>,
                         cudaFuncAttributeMaxDynamicSharedMemorySize, GEMM_SMEM);

    const size_t WSZ = (size_t)D_HID * D_HID;

    // 1) fused prep
    prep_kernel<<<16392, 256>>>(inputs, context, Wq, Wk, Wv, Wo, bk, bv);

    // 2) Q projection (N=1024, fp16 out)
    {
        dim3 g(8, 16);
        gemm_f16<1><<<g, 256, GEMM_SMEM>>>(inh, wth + 0*WSZ, bq, q16, D_HID);
    }
    // 3) K+V merged projection (N=2048, fp16 out)
    {
        dim3 g(16, 16);
        gemm_f16<1><<<g, 256, GEMM_SMEM>>>(cxh, wth + 1*WSZ, bkv, kv16, 2 * D_HID);
    }

    // 4) fused vectorized RoPE + head-attention + scrambled fp16 ctx
    int write_attn = (out_size >= OUT_MAIN + ATTN_ELEMS) ? 1 : 0;
    attn_fused_kernel<<<MROWS, 256>>>(out + OUT_MAIN, write_attn);

    // 5) final projection (fp32 out to d_out)
    {
        dim3 g(8, 16);
        gemm_f16<0><<<g, 256, GEMM_SMEM>>>(xsh, wth + 3*WSZ, bo, out, D_HID);
    }
}

// round 13
// speedup vs baseline: 5.3814x; 1.0364x over previous
#include <cuda_runtime.h>
#include <cuda_fp16.h>
#include <math.h>
#include <stdint.h>

// Shapes (fixed)
#define D_HID 1024
#define SEQ   2048
#define BATCH 2
#define HEADS 16
#define HD    64
#define MROWS (BATCH*SEQ)                 // 4096
#define OUT_MAIN (MROWS*D_HID)            // 4194304
#define ATTN_ELEMS (MROWS*HEADS*HEADS)    // 1048576

// fp16 q/kv planes (GEMM outputs)
__device__ __half g_q16 [MROWS*D_HID];
__device__ __half g_kv16[MROWS*2*D_HID];  // packed rows: k | v
__device__ float  g_bkv[2*D_HID];         // bk || bv
__device__ float  g_cos[SEQ*(D_HID/2)];
__device__ float  g_sin[SEQ*(D_HID/2)];

// fp16 operand planes
__device__ __half g_in_h[MROWS*D_HID];
__device__ __half g_cx_h[MROWS*D_HID];
__device__ __half g_xs_h[MROWS*D_HID];
__device__ __half g_wt_h[4*D_HID*D_HID];  // W^T (Wq,Wk,Wv,Wo)

__device__ __forceinline__ uint32_t smem_u32(const void* p) {
    uint32_t a;
    asm("{ .reg .u64 t; cvta.to.shared.u64 t, %1; cvt.u32.u64 %0, t; }"
        : "=r"(a) : "l"(p));
    return a;
}

// ---------------------------------------------------------------------------
// Fused prep kernel (unchanged)
// ---------------------------------------------------------------------------
__global__ __launch_bounds__(256)
void prep_kernel(const float* __restrict__ inputs, const float* __restrict__ context,
                 const float* __restrict__ W0, const float* __restrict__ W1,
                 const float* __restrict__ W2, const float* __restrict__ W3,
                 const float* __restrict__ bk, const float* __restrict__ bv)
{
    int blk = blockIdx.x;
    int tid = threadIdx.x;

    if (blk < 8192) {
        int which = blk >> 12;
        int idx = ((blk & 4095) << 8) | tid;
        const float4* src = (const float4*)(which ? context : inputs);
        uint2* h = (uint2*)(which ? g_cx_h : g_in_h);
        float4 v = src[idx];
        __half2 p0 = __floats2half2_rn(v.x, v.y);
        __half2 p1 = __floats2half2_rn(v.z, v.w);
        uint2 u;
        u.x = *(uint32_t*)&p0;
        u.y = *(uint32_t*)&p1;
        h[idx] = u;
    } else if (blk < 12288) {
        __shared__ float t[32][33];
        int r  = blk - 8192;
        int z  = r >> 10;
        int bi = r & 1023;
        int x0 = (bi & 31) * 32;
        int y0 = (bi >> 5) * 32;
        const float* W = (z == 0) ? W0 : (z == 1) ? W1 : (z == 2) ? W2 : W3;
        __half* h = g_wt_h + (size_t)z * D_HID * D_HID;
        int tx = tid & 31, ty = tid >> 5;
        #pragma unroll
        for (int j = 0; j < 4; j++)
            t[ty + 8 * j][tx] = W[(size_t)(y0 + ty + 8 * j) * D_HID + x0 + tx];
        __syncthreads();
        #pragma unroll
        for (int j = 0; j < 4; j++) {
            int rr = ty + 8 * j;
            h[(size_t)(x0 + rr) * D_HID + y0 + tx] = __float2half_rn(t[tx][rr]);
        }
    } else if (blk < 16384) {
        int idx = ((blk - 12288) << 8) | tid;
        int s = idx >> 9;
        int j = idx & 511;
        float inv = expf(-(float)j * (9.210340371976184f / 512.0f));
        float arg = (float)s * inv;
        float sv, cv;
        sincosf(arg, &sv, &cv);
        g_cos[idx] = cv;
        g_sin[idx] = sv;
    } else {
        int i = ((blk - 16384) << 8) | tid;
        g_bkv[i] = (i < D_HID) ? bk[i] : bv[i - D_HID];
    }
}

// ---------------------------------------------------------------------------
// fp16 GEMM body (shared by the merged QKV kernel and the O kernel)
//   CTA 256x128, 8 warps of 64x64, K-chunk 32, 4-stage cp.async.
// ---------------------------------------------------------------------------
#define KC 32
#define NSTAGE 4
#define PLANE_A 16384
#define PLANE_B 8192
#define STAGE_BYTES (PLANE_A + PLANE_B)      // 24576
#define GEMM_SMEM (NSTAGE*STAGE_BYTES)       // 98304
#define NCHUNK (D_HID/KC)

#define LDSM4(r0,r1,r2,r3,addr) \
    asm volatile("ldmatrix.sync.aligned.m8n8.x4.shared.b16 {%0,%1,%2,%3}, [%4];" \
        : "=r"(r0), "=r"(r1), "=r"(r2), "=r"(r3) : "r"(addr))

#define MMA_F16(d, a, b0v, b1v) \
    asm volatile("mma.sync.aligned.m16n8k16.row.col.f32.f16.f16.f32 " \
        "{%0,%1,%2,%3}, {%4,%5,%6,%7}, {%8,%9}, {%0,%1,%2,%3};" \
        : "+f"((d)[0]), "+f"((d)[1]), "+f"((d)[2]), "+f"((d)[3]) \
        : "r"((a)[0]), "r"((a)[1]), "r"((a)[2]), "r"((a)[3]), "r"(b0v), "r"(b1v))

template<int OUT_HALF>
__device__ __forceinline__
void gemm_body(const __half* __restrict__ Ah,
               const __half* __restrict__ Bh,
               const float* __restrict__ bias, void* __restrict__ Cv,
               int ldc, int nbaseB)
{
    extern __shared__ char smem[];
    uint32_t sb = smem_u32(smem);
    int tid = threadIdx.x, lane = tid & 31, wid = tid >> 5;
    int wm = (wid & 3) * 64;
    int wn = (wid >> 2) * 64;

    int mbaseA = blockIdx.y * 256;

    int lrow = tid >> 1;
    int lb0  = (tid & 1) * 2;

    uint32_t aOff[4]; int aSw[4];
    #pragma unroll
    for (int mt = 0; mt < 4; mt++) {
        int r = wm + mt * 16 + (lane & 7) + ((lane >> 3) & 1) * 8;
        aOff[mt] = r * 64;
        aSw[mt] = (r >> 1) & 3;
    }
    int g = lane >> 3;
    uint32_t bOff[4]; int bSw[4];
    #pragma unroll
    for (int pk = 0; pk < 4; pk++) {
        int r = wn + pk * 16 + ((g >> 1) << 3) + (lane & 7);
        bOff[pk] = r * 64;
        bSw[pk] = (r >> 1) & 3;
    }
    int aKb = lane >> 4;
    int bKb = g & 1;

    float acc[4][8][4];
    #pragma unroll
    for (int i = 0; i < 4; i++)
        #pragma unroll
        for (int j = 0; j < 8; j++)
            #pragma unroll
            for (int c = 0; c < 4; c++) acc[i][j][c] = 0.0f;

    #define LOAD_CHUNK(chunk, stage) do {                                        \
        uint32_t st0 = sb + (stage) * STAGE_BYTES;                               \
        int kk = (chunk) * KC;                                                   \
        _Pragma("unroll")                                                        \
        for (int rr = 0; rr < 2; rr++) {                                         \
            int r = lrow + rr * 128;                                             \
            int sw = (r >> 1) & 3;                                               \
            const __half* sh = Ah + (size_t)(mbaseA + r) * D_HID + kk;           \
            _Pragma("unroll")                                                    \
            for (int j = 0; j < 2; j++) {                                        \
                int blk = lb0 + j;                                               \
                uint32_t d = st0 + r * 64 + ((blk ^ sw) << 4);                   \
                asm volatile("cp.async.cg.shared.global [%0], [%1], 16;"         \
                             :: "r"(d), "l"(sh + blk * 8));                      \
            }                                                                    \
        }                                                                        \
        {                                                                        \
            int r = lrow;                                                        \
            int sw = (r >> 1) & 3;                                               \
            const __half* sh = Bh + (size_t)(nbaseB + r) * D_HID + kk;           \
            _Pragma("unroll")                                                    \
            for (int j = 0; j < 2; j++) {                                        \
                int blk = lb0 + j;                                               \
                uint32_t d = st0 + PLANE_A + r * 64 + ((blk ^ sw) << 4);         \
                asm volatile("cp.async.cg.shared.global [%0], [%1], 16;"         \
                             :: "r"(d), "l"(sh + blk * 8));                      \
            }                                                                    \
        }                                                                        \
    } while (0)

    #pragma unroll
    for (int s = 0; s < NSTAGE - 1; s++) {
        LOAD_CHUNK(s, s);
        asm volatile("cp.async.commit_group;");
    }

    for (int i = 0; i < NCHUNK; i++) {
        asm volatile("cp.async.wait_group %0;" :: "n"(NSTAGE - 2));
        __syncthreads();

        if (i + NSTAGE - 1 < NCHUNK)
            LOAD_CHUNK(i + NSTAGE - 1, (i + NSTAGE - 1) & (NSTAGE - 1));
        asm volatile("cp.async.commit_group;");

        uint32_t st = sb + (i & (NSTAGE - 1)) * STAGE_BYTES;
        #pragma unroll
        for (int s = 0; s < 2; s++) {
            uint32_t bh[16];
            #pragma unroll
            for (int pk = 0; pk < 4; pk++) {
                uint32_t ad = st + PLANE_A + bOff[pk]
                            + (((2 * s + bKb) ^ bSw[pk]) << 4);
                LDSM4(bh[pk*4+0], bh[pk*4+1], bh[pk*4+2], bh[pk*4+3], ad);
            }
            uint32_t ah[4][4];
            #pragma unroll
            for (int mt = 0; mt < 4; mt++) {
                uint32_t ad = st + aOff[mt] + (((2 * s + aKb) ^ aSw[mt]) << 4);
                LDSM4(ah[mt][0], ah[mt][1], ah[mt][2], ah[mt][3], ad);
            }
            #pragma unroll
            for (int mt = 0; mt < 4; mt++)
                #pragma unroll
                for (int nt = 0; nt < 8; nt++)
                    MMA_F16(acc[mt][nt], ah[mt], bh[nt*2], bh[nt*2+1]);
        }
    }

    #pragma unroll
    for (int mt = 0; mt < 4; mt++) {
        int row0 = blockIdx.y * 256 + wm + mt * 16 + (lane >> 2);
        #pragma unroll
        for (int nt = 0; nt < 8; nt++) {
            int col = nbaseB + wn + nt * 8 + (lane & 3) * 2;
            float b0 = bias[col], b1 = bias[col + 1];
            float o00 = acc[mt][nt][0] + b0, o01 = acc[mt][nt][1] + b1;
            float o10 = acc[mt][nt][2] + b0, o11 = acc[mt][nt][3] + b1;
            if (OUT_HALF) {
                __half* C = (__half*)Cv;
                __half2 p0 = __floats2half2_rn(o00, o01);
                __half2 p1 = __floats2half2_rn(o10, o11);
                *(__half2*)(C + (size_t)row0 * ldc + col) = p0;
                *(__half2*)(C + (size_t)(row0 + 8) * ldc + col) = p1;
            } else {
                float* C = (float*)Cv;
                float2 v0; v0.x = o00; v0.y = o01;
                float2 v1; v1.x = o10; v1.y = o11;
                *(float2*)(C + (size_t)row0 * ldc + col) = v0;
                *(float2*)(C + (size_t)(row0 + 8) * ldc + col) = v1;
            }
        }
    }
}

// Merged Q + KV projection: grid (24, 16). x<8 -> Q tile, x>=8 -> KV tile.
__global__ __launch_bounds__(256, 1)
void gemm_qkv(const float* __restrict__ bq)
{
    if (blockIdx.x < 8) {
        gemm_body<1>(g_in_h, g_wt_h, bq, g_q16, D_HID, blockIdx.x * 128);
    } else {
        gemm_body<1>(g_cx_h, g_wt_h + (size_t)D_HID * D_HID, g_bkv, g_kv16,
                     2 * D_HID, (blockIdx.x - 8) * 128);
    }
}

// Final O projection (fp32 out)
__global__ __launch_bounds__(256, 1)
void gemm_o(const float* __restrict__ bo, float* __restrict__ out)
{
    gemm_body<0>(g_xs_h, g_wt_h + (size_t)3 * D_HID * D_HID, bo, out,
                 D_HID, blockIdx.x * 128);
}

// ---------------------------------------------------------------------------
// Vectorized fused attention — q fp32 smem (broadcast reads), k/v fp16 smem
// (halved crossbar bytes). Compute fp32.
// ---------------------------------------------------------------------------
#define SROWQ 68      // floats per q row
#define SROWH 72      // halves per k/v row (144B stride, bank-stagger 4 words)

__global__ __launch_bounds__(256) void attn_fused_kernel(float* __restrict__ attn_out,
                                                         int write_attn)
{
    __shared__ float  sq[16 * SROWQ];
    __shared__ __half sk[16 * SROWH];
    __shared__ __half sv[16 * SROWH];
    __shared__ float  sc[16][17];

    int token = blockIdx.x;
    int tid   = threadIdx.x;
    int s     = token & (SEQ - 1);
    int b     = token >> 11;

    const uint2* qrow = (const uint2*)(g_q16  + (size_t)token * D_HID);
    const uint2* krow = (const uint2*)(g_kv16 + (size_t)token * (2 * D_HID));
    const uint2* vrow = krow + (D_HID / 4);

    // ---- load + RoPE (4 elems per thread per tensor) ----
    {
        int i0 = tid * 4;
        int j0 = i0 & 511;
        const float4* cs = (const float4*)(g_cos + (s << 9) + j0);
        const float4* sn = (const float4*)(g_sin + (s << 9) + j0);
        float4 c4 = cs[0], s4 = sn[0];

        uint2 uq  = qrow[tid],       uk  = krow[tid];
        uint2 uqp = qrow[tid ^ 128], ukp = krow[tid ^ 128];
        uint2 uv  = vrow[tid];
        float2 q01 = __half22float2(*(__half2*)&uq.x);
        float2 q23 = __half22float2(*(__half2*)&uq.y);
        float2 qp01 = __half22float2(*(__half2*)&uqp.x);
        float2 qp23 = __half22float2(*(__half2*)&uqp.y);
        float2 k01 = __half22float2(*(__half2*)&uk.x);
        float2 k23 = __half22float2(*(__half2*)&uk.y);
        float2 kp01 = __half22float2(*(__half2*)&ukp.x);
        float2 kp23 = __half22float2(*(__half2*)&ukp.y);

        float sgn = (i0 < 512) ? -1.0f : 1.0f;
        float4 rq;
        float2 rk01, rk23;
        rq.x = q01.x * c4.x + sgn * qp01.x * s4.x;
        rq.y = q01.y * c4.y + sgn * qp01.y * s4.y;
        rq.z = q23.x * c4.z + sgn * qp23.x * s4.z;
        rq.w = q23.y * c4.w + sgn * qp23.y * s4.w;
        rk01.x = k01.x * c4.x + sgn * kp01.x * s4.x;
        rk01.y = k01.y * c4.y + sgn * kp01.y * s4.y;
        rk23.x = k23.x * c4.z + sgn * kp23.x * s4.z;
        rk23.y = k23.y * c4.w + sgn * kp23.y * s4.w;

        int row = tid >> 4;
        int c4i = tid & 15;
        *(float4*)(sq + row * SROWQ + c4i * 4) = rq;
        __half2 hk0 = __floats2half2_rn(rk01.x, rk01.y);
        __half2 hk1 = __floats2half2_rn(rk23.x, rk23.y);
        uint2 ukv;
        ukv.x = *(uint32_t*)&hk0;
        ukv.y = *(uint32_t*)&hk1;
        *(uint2*)(sk + row * SROWH + c4i * 4) = ukv;
        *(uint2*)(sv + row * SROWH + c4i * 4) = uv;   // v stored raw fp16
    }
    __syncthreads();

    int h = tid >> 4, t = tid & 15;
    {
        const float4* q4 = (const float4*)(sq + h * SROWQ);
        const uint4*  k8 = (const uint4*)(sk + t * SROWH);   // 8 halves per read
        float ax = 0.0f, ay = 0.0f, az = 0.0f, aw = 0.0f;
        #pragma unroll
        for (int jj = 0; jj < 8; jj++) {
            float4 a0 = q4[2 * jj], a1 = q4[2 * jj + 1];
            uint4 kk = k8[jj];
            float2 b0 = __half22float2(*(__half2*)&kk.x);
            float2 b1 = __half22float2(*(__half2*)&kk.y);
            float2 b2 = __half22float2(*(__half2*)&kk.z);
            float2 b3 = __half22float2(*(__half2*)&kk.w);
            ax = fmaf(a0.x, b0.x, ax);
            ay = fmaf(a0.y, b0.y, ay);
            az = fmaf(a0.z, b1.x, az);
            aw = fmaf(a0.w, b1.y, aw);
            ax = fmaf(a1.x, b2.x, ax);
            ay = fmaf(a1.y, b2.y, ay);
            az = fmaf(a1.z, b3.x, az);
            aw = fmaf(a1.w, b3.y, aw);
        }
        float sco = (ax + ay + az + aw) * 0.125f;

        float m = sco;
        #pragma unroll
        for (int o = 8; o; o >>= 1)
            m = fmaxf(m, __shfl_xor_sync(0xffffffffu, m, o));
        float e = expf(sco - m);
        float sum = e;
        #pragma unroll
        for (int o = 8; o; o >>= 1)
            sum += __shfl_xor_sync(0xffffffffu, sum, o);
        float p = e / sum;
        sc[h][t] = p;
        if (write_attn)
            attn_out[(size_t)token * 256 + tid] = p;
    }
    __syncthreads();

    {
        int d4 = tid & 15;
        float4 acc = make_float4(0.0f, 0.0f, 0.0f, 0.0f);
        #pragma unroll
        for (int tt = 0; tt < 16; tt++) {
            float p = sc[h][tt];
            uint2 uv = *(const uint2*)(sv + tt * SROWH + d4 * 4);
            float2 v01 = __half22float2(*(__half2*)&uv.x);
            float2 v23 = __half22float2(*(__half2*)&uv.y);
            acc.x = fmaf(p, v01.x, acc.x);
            acc.y = fmaf(p, v01.y, acc.y);
            acc.z = fmaf(p, v23.x, acc.z);
            acc.w = fmaf(p, v23.y, acc.w);
        }
        size_t xbase = ((size_t)b * SEQ + (h * 128 + (s >> 4))) * D_HID
                     + ((s & 15) << 6) + d4 * 4;
        __half2 p0 = __floats2half2_rn(acc.x, acc.y);
        __half2 p1 = __floats2half2_rn(acc.z, acc.w);
        uint2 u;
        u.x = *(uint32_t*)&p0;
        u.y = *(uint32_t*)&p1;
        *(uint2*)(g_xs_h + xbase) = u;
    }
}

// ---------------------------------------------------------------------------
extern "C" void kernel_launch(void* const* d_in, const int* in_sizes, int n_in,
                              void* d_out, int out_size)
{
    const float* inputs  = (const float*)d_in[0];
    const float* context = (const float*)d_in[1];
    const float* Wq = (const float*)d_in[2];
    const float* bq = (const float*)d_in[3];
    const float* Wk = (const float*)d_in[4];
    const float* bk = (const float*)d_in[5];
    const float* Wv = (const float*)d_in[6];
    const float* bv = (const float*)d_in[7];
    const float* Wo = (const float*)d_in[8];
    const float* bo = (const float*)d_in[9];
    float* out = (float*)d_out;

    cudaFuncSetAttribute(gemm_qkv,
                         cudaFuncAttributeMaxDynamicSharedMemorySize, GEMM_SMEM);
    cudaFuncSetAttribute(gemm_o,
                         cudaFuncAttributeMaxDynamicSharedMemorySize, GEMM_SMEM);

    // 1) fused prep
    prep_kernel<<<16392, 256>>>(inputs, context, Wq, Wk, Wv, Wo, bk, bv);

    // 2) merged Q + K/V projections (one launch, 384 CTAs)
    {
        dim3 g(24, 16);
        gemm_qkv<<<g, 256, GEMM_SMEM>>>(bq);
    }

    // 3) fused vectorized RoPE + head-attention + scrambled fp16 ctx
    int write_attn = (out_size >= OUT_MAIN + ATTN_ELEMS) ? 1 : 0;
    attn_fused_kernel<<<MROWS, 256>>>(out + OUT_MAIN, write_attn);

    // 4) final projection (fp32 out to d_out)
    {
        dim3 g(8, 16);
        gemm_o<<<g, 256, GEMM_SMEM>>>(bo, out);
    }
}